// round 9
// baseline (speedup 1.0000x reference)
#include <cuda_runtime.h>
#include <math.h>
#include <stdint.h>

// Problem shape (fixed by the dataset)
#define BATCH   4
#define S_LEN   2048
#define DMODEL  1024
#define NHEAD   16
#define HD      64
#define MTOK    (BATCH * S_LEN)        // 8192 token rows

// ---------------------------------------------------------------------------
// Scratch (device globals: allocation-free)
// ---------------------------------------------------------------------------
__device__ __align__(16) float g_qkv[(size_t)MTOK * 3 * DMODEL];   // fp32 qkv
__device__ __align__(16) float g_attn[(size_t)MTOK * DMODEL];      // fp32 attn out

__device__ __forceinline__ uint32_t f32_to_tf32(float v) {
    uint32_t b;
    asm("cvt.rna.tf32.f32 %0, %1;" : "=r"(b) : "f"(v));
    return b;
}

__device__ __forceinline__ void mma_tf32(float* c, const uint32_t* a,
                                         const uint32_t* b) {
    asm volatile(
        "mma.sync.aligned.m16n8k8.row.col.f32.tf32.tf32.f32 "
        "{%0,%1,%2,%3}, {%4,%5,%6,%7}, {%8,%9}, {%0,%1,%2,%3};"
        : "+f"(c[0]), "+f"(c[1]), "+f"(c[2]), "+f"(c[3])
        : "r"(a[0]), "r"(a[1]), "r"(a[2]), "r"(a[3]), "r"(b[0]), "r"(b[1]));
}

__device__ __forceinline__ uint32_t smem_u32(const void* p) {
    uint32_t a;
    asm("{ .reg .u64 t; cvta.to.shared.u64 t, %1; cvt.u32.u64 %0, t; }"
        : "=r"(a) : "l"(p));
    return a;
}
__device__ __forceinline__ void cp_async16(uint32_t dst, const void* src) {
    asm volatile("cp.async.cg.shared.global [%0], [%1], 16;"
                 :: "r"(dst), "l"(src));
}
#define CP_COMMIT()  asm volatile("cp.async.commit_group;" ::: "memory")
#define CP_WAIT1()   asm volatile("cp.async.wait_group 1;" ::: "memory")

// ---------------------------------------------------------------------------
// tf32 tensor-core GEMM, fp32 operands (in-register cvt.rna on fragments).
// C[M,N] = A[M,K] @ B[K,N] + bias[N]
// Block 128x256, BK=16, 256 threads, 8 warps (2m x 4n), warp tile 64x64.
// 3-stage cp.async pipeline. (unchanged from round 8)
// ---------------------------------------------------------------------------
#define GBM 128
#define GBN 256
#define GBK 16
#define ASTR 20
#define BSTR 264
#define A_TW (128 * ASTR)
#define B_TW (GBK * BSTR)
#define STG_W (A_TW + B_TW)
#define GEMM_SMEM_BYTES (3 * STG_W * 4)   // 81408 B

__global__ __launch_bounds__(256, 1) void tf32_gemm_kernel(
    const float* __restrict__ A, const float* __restrict__ B,
    const float* __restrict__ bias, float* __restrict__ C,
    int M, int N, int K)
{
    extern __shared__ float smw[];
    const uint32_t smb = smem_u32(smw);

    const int tid  = threadIdx.x;
    const int wid  = tid >> 5;
    const int lane = tid & 31;
    const int g = lane >> 2;
    const int q = lane & 3;

    const int wm = (wid & 1) << 6;
    const int wn = (wid >> 1) << 6;

    const int bm = blockIdx.y * GBM;
    const int bn = blockIdx.x * GBN;
    const int NT = K / GBK;

    const int a_row = tid >> 2;
    const int a_ch  = (tid & 3) << 2;
    const int b_kr  = tid >> 6;
    const int b_ch  = (tid & 63) << 2;

    auto issue = [&](int s, int kt) {
        uint32_t sb = smb + (uint32_t)(s * STG_W) * 4;
        #pragma unroll
        for (int r = 0; r < 2; r++) {
            int row = a_row + (r << 6);
            cp_async16(sb + (uint32_t)(row * ASTR + a_ch) * 4,
                       A + (size_t)(bm + row) * K + kt * GBK + a_ch);
        }
        uint32_t bb = sb + (uint32_t)A_TW * 4;
        #pragma unroll
        for (int r = 0; r < 4; r++) {
            int kr = b_kr + (r << 2);
            cp_async16(bb + (uint32_t)(kr * BSTR + b_ch) * 4,
                       B + (size_t)(kt * GBK + kr) * N + bn + b_ch);
        }
    };

    float acc[4][8][4];
    #pragma unroll
    for (int mi = 0; mi < 4; mi++)
        #pragma unroll
        for (int ni = 0; ni < 8; ni++)
            #pragma unroll
            for (int r = 0; r < 4; r++) acc[mi][ni][r] = 0.0f;

    issue(0, 0); CP_COMMIT();
    issue(1, 1); CP_COMMIT();

    for (int kt = 0; kt < NT; kt++) {
        CP_WAIT1();
        __syncthreads();
        if (kt + 2 < NT) issue((kt + 2) % 3, kt + 2);
        CP_COMMIT();

        const float* As = smw + (kt % 3) * STG_W;
        const float* Bs = As + A_TW;

        #pragma unroll
        for (int k8 = 0; k8 < GBK; k8 += 8) {
            uint32_t af[4][4], bf[8][2];
            #pragma unroll
            for (int mi = 0; mi < 4; mi++) {
                const float* ar = As + (wm + (mi << 4) + g) * ASTR + k8 + q;
                af[mi][0] = f32_to_tf32(ar[0]);
                af[mi][1] = f32_to_tf32(ar[8 * ASTR]);
                af[mi][2] = f32_to_tf32(ar[4]);
                af[mi][3] = f32_to_tf32(ar[8 * ASTR + 4]);
            }
            #pragma unroll
            for (int ni = 0; ni < 8; ni++) {
                const float* br = Bs + (k8 + q) * BSTR + wn + (ni << 3) + g;
                bf[ni][0] = f32_to_tf32(br[0]);
                bf[ni][1] = f32_to_tf32(br[4 * BSTR]);
            }
            #pragma unroll
            for (int mi = 0; mi < 4; mi++)
                #pragma unroll
                for (int ni = 0; ni < 8; ni++)
                    mma_tf32(acc[mi][ni], af[mi], bf[ni]);
        }
    }

    #pragma unroll
    for (int mi = 0; mi < 4; mi++) {
        int m = bm + wm + (mi << 4) + g;
        #pragma unroll
        for (int ni = 0; ni < 8; ni++) {
            int n = bn + wn + (ni << 3) + (q << 1);
            float2 bb = *(const float2*)&bias[n];
            float2 o0, o1;
            o0.x = acc[mi][ni][0] + bb.x;
            o0.y = acc[mi][ni][1] + bb.y;
            o1.x = acc[mi][ni][2] + bb.x;
            o1.y = acc[mi][ni][3] + bb.y;
            *(float2*)&C[(size_t)m * N + n]       = o0;
            *(float2*)&C[(size_t)(m + 8) * N + n] = o1;
        }
    }
}

// ---------------------------------------------------------------------------
// Flash attention on tensor cores (tf32 mma.sync), causal.
// Q-tile = 128 rows, 8 warps (warp = 16 rows), 256 threads.
// Synchronous K/V staging (proven structure), K-iter = 64 keys.
// smem: Qs[128][68] tf32, Ks[64][68] tf32, Vs[64][72] tf32, Ps[128][68] tf32
// ---------------------------------------------------------------------------
#define BQ  128
#define AQS 68
#define AVS 72
#define ATTN_SMEM_BYTES ((BQ*AQS + 64*AQS + 64*AVS + BQ*AQS) * 4)  // 105472 B

__global__ __launch_bounds__(256) void attn_mma_kernel()
{
    extern __shared__ uint32_t smu[];
    uint32_t* Qs = smu;                    // [128][68]
    uint32_t* Ks = Qs + BQ * AQS;          // [64][68]
    uint32_t* Vs = Ks + 64 * AQS;          // [64][72]
    uint32_t* Ps = Vs + 64 * AVS;          // [128][68]

    const int tid  = threadIdx.x;
    const int wid  = tid >> 5;             // 0..7
    const int lane = tid & 31;
    const int g = lane >> 2;
    const int q = lane & 3;

    const int qt = blockIdx.x;             // 0..15
    const int bh = blockIdx.y;             // 0..63
    const int b  = bh >> 4;
    const int h  = bh & (NHEAD - 1);

    const int q0 = qt * BQ;
    const int qr = wid << 4;               // warp row base 0..112
    const float NEG = -1e30f;

    // load Q tile: 128 rows x 64 cols (fp32 -> tf32)
    for (int i = tid; i < 2048; i += 256) {
        int row = i >> 4, c4 = (i & 15) << 2;
        float4 v = *(const float4*)(g_qkv
            + (size_t)(b * S_LEN + q0 + row) * (3 * DMODEL) + h * HD + c4);
        uint4 o;
        o.x = f32_to_tf32(v.x); o.y = f32_to_tf32(v.y);
        o.z = f32_to_tf32(v.z); o.w = f32_to_tf32(v.w);
        *(uint4*)&Qs[row * AQS + c4] = o;
    }

    float O[8][4];
    #pragma unroll
    for (int ni = 0; ni < 8; ni++)
        #pragma unroll
        for (int r = 0; r < 4; r++) O[ni][r] = 0.0f;
    float mrow0 = NEG, mrow1 = NEG, lrow0 = 0.0f, lrow1 = 0.0f;

    const int nkt = 2 * qt + 2;            // k-tiles of 64 keys

    for (int kt = 0; kt < nkt; kt++) {
        const int k0 = kt * 64;
        __syncthreads();
        // stage K & V (64 rows x 64 cols each)
        for (int i = tid; i < 1024; i += 256) {
            int row = i >> 4, c4 = (i & 15) << 2;
            const float* base = g_qkv
                + (size_t)(b * S_LEN + k0 + row) * (3 * DMODEL)
                + DMODEL + h * HD + c4;
            float4 kv = *(const float4*)base;
            float4 vv = *(const float4*)(base + DMODEL);
            uint4 ok, ov;
            ok.x = f32_to_tf32(kv.x); ok.y = f32_to_tf32(kv.y);
            ok.z = f32_to_tf32(kv.z); ok.w = f32_to_tf32(kv.w);
            ov.x = f32_to_tf32(vv.x); ov.y = f32_to_tf32(vv.y);
            ov.z = f32_to_tf32(vv.z); ov.w = f32_to_tf32(vv.w);
            *(uint4*)&Ks[row * AQS + c4] = ok;
            *(uint4*)&Vs[row * AVS + c4] = ov;
        }
        __syncthreads();

        // warp rows [q0+qr, q0+qr+15]; skip tiles entirely above the diagonal
        if (k0 > q0 + qr + 15) continue;

        // S = Q @ K^T  (warp: 16 x 64)
        float s[8][4];
        #pragma unroll
        for (int ni = 0; ni < 8; ni++)
            #pragma unroll
            for (int r = 0; r < 4; r++) s[ni][r] = 0.0f;

        #pragma unroll
        for (int k8 = 0; k8 < 64; k8 += 8) {
            uint32_t a[4];
            a[0] = Qs[(qr + g) * AQS + k8 + q];
            a[1] = Qs[(qr + g + 8) * AQS + k8 + q];
            a[2] = Qs[(qr + g) * AQS + k8 + q + 4];
            a[3] = Qs[(qr + g + 8) * AQS + k8 + q + 4];
            #pragma unroll
            for (int ni = 0; ni < 8; ni++) {
                uint32_t bb[2];
                bb[0] = Ks[(ni * 8 + g) * AQS + k8 + q];
                bb[1] = Ks[(ni * 8 + g) * AQS + k8 + q + 4];
                mma_tf32(s[ni], a, bb);
            }
        }

        // scale + causal mask (global-index compare when tile straddles rows)
        #pragma unroll
        for (int ni = 0; ni < 8; ni++)
            #pragma unroll
            for (int r = 0; r < 4; r++) s[ni][r] *= 0.125f;
        if (k0 + 63 > q0 + qr) {
            int r0 = q0 + qr + g, r1 = r0 + 8;
            #pragma unroll
            for (int ni = 0; ni < 8; ni++) {
                int c = k0 + ni * 8 + (q << 1);
                if (c > r0)     s[ni][0] = NEG;
                if (c + 1 > r0) s[ni][1] = NEG;
                if (c > r1)     s[ni][2] = NEG;
                if (c + 1 > r1) s[ni][3] = NEG;
            }
        }

        // online softmax (rows g, g+8; reduce over 4 q-lanes)
        float mx0 = NEG, mx1 = NEG;
        #pragma unroll
        for (int ni = 0; ni < 8; ni++) {
            mx0 = fmaxf(mx0, fmaxf(s[ni][0], s[ni][1]));
            mx1 = fmaxf(mx1, fmaxf(s[ni][2], s[ni][3]));
        }
        mx0 = fmaxf(mx0, __shfl_xor_sync(0xffffffffu, mx0, 1));
        mx0 = fmaxf(mx0, __shfl_xor_sync(0xffffffffu, mx0, 2));
        mx1 = fmaxf(mx1, __shfl_xor_sync(0xffffffffu, mx1, 1));
        mx1 = fmaxf(mx1, __shfl_xor_sync(0xffffffffu, mx1, 2));

        float mn0 = fmaxf(mrow0, mx0), mn1 = fmaxf(mrow1, mx1);
        float corr0 = __expf(mrow0 - mn0), corr1 = __expf(mrow1 - mn1);
        float sum0 = 0.0f, sum1 = 0.0f;
        #pragma unroll
        for (int ni = 0; ni < 8; ni++) {
            s[ni][0] = __expf(s[ni][0] - mn0);
            s[ni][1] = __expf(s[ni][1] - mn0);
            s[ni][2] = __expf(s[ni][2] - mn1);
            s[ni][3] = __expf(s[ni][3] - mn1);
            sum0 += s[ni][0] + s[ni][1];
            sum1 += s[ni][2] + s[ni][3];
        }
        sum0 += __shfl_xor_sync(0xffffffffu, sum0, 1);
        sum0 += __shfl_xor_sync(0xffffffffu, sum0, 2);
        sum1 += __shfl_xor_sync(0xffffffffu, sum1, 1);
        sum1 += __shfl_xor_sync(0xffffffffu, sum1, 2);
        lrow0 = lrow0 * corr0 + sum0;
        lrow1 = lrow1 * corr1 + sum1;
        mrow0 = mn0; mrow1 = mn1;
        #pragma unroll
        for (int ni = 0; ni < 8; ni++) {
            O[ni][0] *= corr0; O[ni][1] *= corr0;
            O[ni][2] *= corr1; O[ni][3] *= corr1;
        }

        // P -> smem (tf32), warp-private stripe
        #pragma unroll
        for (int ni = 0; ni < 8; ni++) {
            int c = ni * 8 + (q << 1);
            uint2 p0, p1;
            p0.x = f32_to_tf32(s[ni][0]); p0.y = f32_to_tf32(s[ni][1]);
            p1.x = f32_to_tf32(s[ni][2]); p1.y = f32_to_tf32(s[ni][3]);
            *(uint2*)&Ps[(qr + g) * AQS + c]     = p0;
            *(uint2*)&Ps[(qr + g + 8) * AQS + c] = p1;
        }
        __syncwarp();

        // O += P @ V
        #pragma unroll
        for (int k8 = 0; k8 < 64; k8 += 8) {
            uint32_t a[4];
            a[0] = Ps[(qr + g) * AQS + k8 + q];
            a[1] = Ps[(qr + g + 8) * AQS + k8 + q];
            a[2] = Ps[(qr + g) * AQS + k8 + q + 4];
            a[3] = Ps[(qr + g + 8) * AQS + k8 + q + 4];
            #pragma unroll
            for (int ni = 0; ni < 8; ni++) {
                uint32_t bb[2];
                bb[0] = Vs[(k8 + q) * AVS + ni * 8 + g];
                bb[1] = Vs[(k8 + q + 4) * AVS + ni * 8 + g];
                mma_tf32(O[ni], a, bb);
            }
        }
    }

    // normalize + store fp32
    float inv0 = 1.0f / lrow0, inv1 = 1.0f / lrow1;
    int r0 = q0 + qr + g, r1 = r0 + 8;
    float* d0 = g_attn + (size_t)(b * S_LEN + r0) * DMODEL + h * HD;
    float* d1 = g_attn + (size_t)(b * S_LEN + r1) * DMODEL + h * HD;
    #pragma unroll
    for (int ni = 0; ni < 8; ni++) {
        int c = ni * 8 + (q << 1);
        float2 o0, o1;
        o0.x = O[ni][0] * inv0; o0.y = O[ni][1] * inv0;
        o1.x = O[ni][2] * inv1; o1.y = O[ni][3] * inv1;
        *(float2*)&d0[c] = o0;
        *(float2*)&d1[c] = o1;
    }
}

// ---------------------------------------------------------------------------
// kernel_launch: x, w_qkv, b_qkv, w_proj, b_proj
// ---------------------------------------------------------------------------
extern "C" void kernel_launch(void* const* d_in, const int* in_sizes, int n_in,
                              void* d_out, int out_size)
{
    const float* x      = (const float*)d_in[0];
    const float* w_qkv  = (const float*)d_in[1];
    const float* b_qkv  = (const float*)d_in[2];
    const float* w_proj = (const float*)d_in[3];
    const float* b_proj = (const float*)d_in[4];
    float* out = (float*)d_out;

    void *qkv, *attn;
    cudaGetSymbolAddress(&qkv, g_qkv);
    cudaGetSymbolAddress(&attn, g_attn);

    cudaFuncSetAttribute(tf32_gemm_kernel,
                         cudaFuncAttributeMaxDynamicSharedMemorySize,
                         GEMM_SMEM_BYTES);
    cudaFuncSetAttribute(attn_mma_kernel,
                         cudaFuncAttributeMaxDynamicSharedMemorySize,
                         ATTN_SMEM_BYTES);

    // 1) QKV projection: [8192,1024] @ [1024,3072] + b
    {
        dim3 grid(3 * DMODEL / GBN, MTOK / GBM);
        tf32_gemm_kernel<<<grid, 256, GEMM_SMEM_BYTES>>>(
            x, w_qkv, b_qkv, (float*)qkv, MTOK, 3 * DMODEL, DMODEL);
    }

    // 2) causal flash attention on tensor cores (128-row q-tiles)
    {
        dim3 grid(S_LEN / BQ, BATCH * NHEAD);
        attn_mma_kernel<<<grid, 256, ATTN_SMEM_BYTES>>>();
    }

    // 3) output projection: [8192,1024] @ [1024,1024] + b
    {
        dim3 grid(DMODEL / GBN, MTOK / GBM);
        tf32_gemm_kernel<<<grid, 256, GEMM_SMEM_BYTES>>>(
            (const float*)attn, w_proj, b_proj, out, MTOK, DMODEL, DMODEL);
    }
}

// round 10
// speedup vs baseline: 1.3259x; 1.3259x over previous
#include <cuda_runtime.h>
#include <cuda_fp16.h>
#include <math.h>
#include <stdint.h>

// Problem shape (fixed by the dataset)
#define BATCH   4
#define S_LEN   2048
#define DMODEL  1024
#define NHEAD   16
#define HD      64
#define MTOK    (BATCH * S_LEN)        // 8192 token rows

// ---------------------------------------------------------------------------
// Scratch (device globals: allocation-free)
// ---------------------------------------------------------------------------
__device__ __align__(16) __half g_x_h[(size_t)MTOK * DMODEL];          // x fp16
__device__ __align__(16) __half g_wqkv_h[(size_t)3 * DMODEL * DMODEL]; // w_qkv^T [N][K]
__device__ __align__(16) __half g_wproj_h[(size_t)DMODEL * DMODEL];    // w_proj^T [N][K]
__device__ __align__(16) float  g_qkv[(size_t)MTOK * 3 * DMODEL];      // fp32 qkv
__device__ __align__(16) float  g_attn[(size_t)MTOK * DMODEL];         // fp32 attn out
__device__ __align__(16) __half g_attn_h[(size_t)MTOK * DMODEL];       // attn out fp16

__device__ __forceinline__ uint32_t f32_to_tf32(float v) {
    uint32_t b;
    asm("cvt.rna.tf32.f32 %0, %1;" : "=r"(b) : "f"(v));
    return b;
}

__device__ __forceinline__ void mma_tf32(float* c, const uint32_t* a,
                                         const uint32_t* b) {
    asm volatile(
        "mma.sync.aligned.m16n8k8.row.col.f32.tf32.tf32.f32 "
        "{%0,%1,%2,%3}, {%4,%5,%6,%7}, {%8,%9}, {%0,%1,%2,%3};"
        : "+f"(c[0]), "+f"(c[1]), "+f"(c[2]), "+f"(c[3])
        : "r"(a[0]), "r"(a[1]), "r"(a[2]), "r"(a[3]), "r"(b[0]), "r"(b[1]));
}

__device__ __forceinline__ void mma_f16(float* c, const uint32_t* a,
                                        const uint32_t* b) {
    asm volatile(
        "mma.sync.aligned.m16n8k16.row.col.f32.f16.f16.f32 "
        "{%0,%1,%2,%3}, {%4,%5,%6,%7}, {%8,%9}, {%0,%1,%2,%3};"
        : "+f"(c[0]), "+f"(c[1]), "+f"(c[2]), "+f"(c[3])
        : "r"(a[0]), "r"(a[1]), "r"(a[2]), "r"(a[3]), "r"(b[0]), "r"(b[1]));
}

__device__ __forceinline__ uint32_t smem_u32(const void* p) {
    uint32_t a;
    asm("{ .reg .u64 t; cvta.to.shared.u64 t, %1; cvt.u32.u64 %0, t; }"
        : "=r"(a) : "l"(p));
    return a;
}
__device__ __forceinline__ void cp_async16(uint32_t dst, const void* src) {
    asm volatile("cp.async.cg.shared.global [%0], [%1], 16;"
                 :: "r"(dst), "l"(src));
}
#define CP_COMMIT()  asm volatile("cp.async.commit_group;" ::: "memory")
#define CP_WAIT1()   asm volatile("cp.async.wait_group 1;" ::: "memory")

// ---------------------------------------------------------------------------
// fp16 tensor-core GEMM: C[M,N] = A[M,K](f16) @ Bt[N,K](f16)^T + bias[N]
// Block 128x256, BK=32 (2 x k16), 256 threads, 8 warps (2m x 4n), warp 64x64.
// 3-stage cp.async pipeline.
// A/B smem rows: 32 fp16 data + 8 pad = 40 fp16 = 20 words (bank 20g+q, clean).
// ---------------------------------------------------------------------------
#define GBM 128
#define GBN 256
#define GBK 32
#define KPW 20                        // uint32 words per smem row
#define A_TW (128 * KPW)              // 2560 words
#define B_TW (256 * KPW)              // 5120 words
#define STG_W (A_TW + B_TW)           // 7680 words
#define GEMM_SMEM_BYTES (3 * STG_W * 4)   // 92160 B

__global__ __launch_bounds__(256, 1) void f16_gemm_kernel(
    const __half* __restrict__ A, const __half* __restrict__ Bt,
    const float* __restrict__ bias, float* __restrict__ C,
    int M, int N, int K)
{
    extern __shared__ uint32_t smw[];
    const uint32_t smb = smem_u32(smw);

    const int tid  = threadIdx.x;
    const int wid  = tid >> 5;
    const int lane = tid & 31;
    const int g = lane >> 2;          // 0..7
    const int q = lane & 3;           // 0..3

    const int wm = (wid & 1) << 6;    // 0 or 64
    const int wn = (wid >> 1) << 6;   // 0,64,128,192

    const int bm = blockIdx.y * GBM;
    const int bn = blockIdx.x * GBN;
    const int NT = K / GBK;

    // cp.async: A = 128 rows x 2 chunks(16 fp16) ; B = 256 rows x 2 chunks
    const int c_row = tid >> 1;            // 0..127
    const int c_h   = (tid & 1) << 4;      // fp16 offset 0 or 16
    const int c_w   = (tid & 1) << 3;      // word offset 0 or 8

    auto issue = [&](int s, int kt) {
        uint32_t sb = smb + (uint32_t)(s * STG_W) * 4;
        const __half* Ar = A + (size_t)(bm + c_row) * K + kt * GBK + c_h;
        uint32_t ad = sb + (uint32_t)(c_row * KPW + c_w) * 4;
        cp_async16(ad, Ar);
        cp_async16(ad + 16, Ar + 8);
        uint32_t bb = sb + (uint32_t)A_TW * 4;
        #pragma unroll
        for (int r = 0; r < 2; r++) {
            int row = c_row + (r << 7);
            const __half* Br = Bt + (size_t)(bn + row) * K + kt * GBK + c_h;
            uint32_t bd = bb + (uint32_t)(row * KPW + c_w) * 4;
            cp_async16(bd, Br);
            cp_async16(bd + 16, Br + 8);
        }
    };

    float acc[4][8][4];
    #pragma unroll
    for (int mi = 0; mi < 4; mi++)
        #pragma unroll
        for (int ni = 0; ni < 8; ni++)
            #pragma unroll
            for (int r = 0; r < 4; r++) acc[mi][ni][r] = 0.0f;

    issue(0, 0); CP_COMMIT();
    issue(1, 1); CP_COMMIT();

    for (int kt = 0; kt < NT; kt++) {
        CP_WAIT1();
        __syncthreads();
        if (kt + 2 < NT) issue((kt + 2) % 3, kt + 2);
        CP_COMMIT();

        const uint32_t* As = smw + (kt % 3) * STG_W;
        const uint32_t* Bs = As + A_TW;

        #pragma unroll
        for (int s16 = 0; s16 < 2; s16++) {
            const int s8 = s16 << 3;   // word offset of this k16 step
            uint32_t af[4][4], bf[8][2];
            #pragma unroll
            for (int mi = 0; mi < 4; mi++) {
                const uint32_t* ar = As + (wm + (mi << 4) + g) * KPW + s8 + q;
                af[mi][0] = ar[0];
                af[mi][1] = ar[8 * KPW];
                af[mi][2] = ar[4];
                af[mi][3] = ar[8 * KPW + 4];
            }
            #pragma unroll
            for (int ni = 0; ni < 8; ni++) {
                const uint32_t* br = Bs + (wn + (ni << 3) + g) * KPW + s8 + q;
                bf[ni][0] = br[0];
                bf[ni][1] = br[4];
            }
            #pragma unroll
            for (int mi = 0; mi < 4; mi++)
                #pragma unroll
                for (int ni = 0; ni < 8; ni++)
                    mma_f16(acc[mi][ni], af[mi], bf[ni]);
        }
    }

    // epilogue (c0,c1)=(row g, cols 2q,2q+1), (c2,c3)=(row g+8)
    #pragma unroll
    for (int mi = 0; mi < 4; mi++) {
        int m = bm + wm + (mi << 4) + g;
        #pragma unroll
        for (int ni = 0; ni < 8; ni++) {
            int n = bn + wn + (ni << 3) + (q << 1);
            float2 bb = *(const float2*)&bias[n];
            float2 o0, o1;
            o0.x = acc[mi][ni][0] + bb.x;
            o0.y = acc[mi][ni][1] + bb.y;
            o1.x = acc[mi][ni][2] + bb.x;
            o1.y = acc[mi][ni][3] + bb.y;
            *(float2*)&C[(size_t)m * N + n]       = o0;
            *(float2*)&C[(size_t)(m + 8) * N + n] = o1;
        }
    }
}

// ---------------------------------------------------------------------------
// Prepass: fp32 -> fp16 elementwise (rn)
// ---------------------------------------------------------------------------
__global__ void cvt_f16_kernel(const float4* __restrict__ src,
                               __half2* __restrict__ dst, int n4)
{
    int i = blockIdx.x * blockDim.x + threadIdx.x;
    if (i < n4) {
        float4 v = src[i];
        dst[i * 2]     = __floats2half2_rn(v.x, v.y);
        dst[i * 2 + 1] = __floats2half2_rn(v.z, v.w);
    }
}

// Prepass: dst[n*K+k] = fp16(src[k*N+n])  (transpose-convert weights)
__global__ void transpose_f16_kernel(const float* __restrict__ src,
                                     __half* __restrict__ dst, int K, int N)
{
    __shared__ __half t[32][33];
    const int n0 = blockIdx.x * 32, k0 = blockIdx.y * 32;
    const int tx = threadIdx.x, ty = threadIdx.y;   // 32x8
    #pragma unroll
    for (int i = ty; i < 32; i += 8)
        t[i][tx] = __float2half_rn(src[(size_t)(k0 + i) * N + n0 + tx]);
    __syncthreads();
    #pragma unroll
    for (int i = ty; i < 32; i += 8)
        dst[(size_t)(n0 + i) * K + k0 + tx] = t[tx][i];
}

// ---------------------------------------------------------------------------
// Flash attention on tensor cores (tf32 mma.sync), causal.
// EXACT round-8 passing version (64-row q-tile, synchronous K/V staging).
// ---------------------------------------------------------------------------
#define AQS 68
#define AVS 72
#define ATTN_SMEM_BYTES ((64*AQS*3 + 64*AVS) * 4)

__global__ __launch_bounds__(128) void attn_mma_kernel()
{
    extern __shared__ uint32_t smu[];
    uint32_t* Qs = smu;
    uint32_t* Ks = Qs + 64 * AQS;
    uint32_t* Vs = Ks + 64 * AQS;
    uint32_t* Ps = Vs + 64 * AVS;

    const int tid  = threadIdx.x;
    const int wid  = tid >> 5;
    const int lane = tid & 31;
    const int g = lane >> 2;
    const int q = lane & 3;

    const int qt = blockIdx.x;
    const int bh = blockIdx.y;
    const int b  = bh >> 4;
    const int h  = bh & (NHEAD - 1);

    const int q0 = qt * 64;
    const int qr = wid << 4;
    const float NEG = -1e30f;

    for (int i = tid; i < 1024; i += 128) {
        int row = i >> 4, c4 = (i & 15) << 2;
        float4 v = *(const float4*)(g_qkv
            + (size_t)(b * S_LEN + q0 + row) * (3 * DMODEL) + h * HD + c4);
        uint4 o;
        o.x = f32_to_tf32(v.x); o.y = f32_to_tf32(v.y);
        o.z = f32_to_tf32(v.z); o.w = f32_to_tf32(v.w);
        *(uint4*)&Qs[row * AQS + c4] = o;
    }

    float O[8][4];
    #pragma unroll
    for (int ni = 0; ni < 8; ni++)
        #pragma unroll
        for (int r = 0; r < 4; r++) O[ni][r] = 0.0f;
    float mrow0 = NEG, mrow1 = NEG, lrow0 = 0.0f, lrow1 = 0.0f;

    for (int kt = 0; kt <= qt; kt++) {
        const int k0 = kt * 64;
        __syncthreads();
        for (int i = tid; i < 1024; i += 128) {
            int row = i >> 4, c4 = (i & 15) << 2;
            const float* base = g_qkv
                + (size_t)(b * S_LEN + k0 + row) * (3 * DMODEL)
                + DMODEL + h * HD + c4;
            float4 kv = *(const float4*)base;
            float4 vv = *(const float4*)(base + DMODEL);
            uint4 ok, ov;
            ok.x = f32_to_tf32(kv.x); ok.y = f32_to_tf32(kv.y);
            ok.z = f32_to_tf32(kv.z); ok.w = f32_to_tf32(kv.w);
            ov.x = f32_to_tf32(vv.x); ov.y = f32_to_tf32(vv.y);
            ov.z = f32_to_tf32(vv.z); ov.w = f32_to_tf32(vv.w);
            *(uint4*)&Ks[row * AQS + c4] = ok;
            *(uint4*)&Vs[row * AVS + c4] = ov;
        }
        __syncthreads();

        float s[8][4];
        #pragma unroll
        for (int ni = 0; ni < 8; ni++)
            #pragma unroll
            for (int r = 0; r < 4; r++) s[ni][r] = 0.0f;

        #pragma unroll
        for (int k8 = 0; k8 < 64; k8 += 8) {
            uint32_t a[4];
            a[0] = Qs[(qr + g) * AQS + k8 + q];
            a[1] = Qs[(qr + g + 8) * AQS + k8 + q];
            a[2] = Qs[(qr + g) * AQS + k8 + q + 4];
            a[3] = Qs[(qr + g + 8) * AQS + k8 + q + 4];
            #pragma unroll
            for (int ni = 0; ni < 8; ni++) {
                uint32_t bb[2];
                bb[0] = Ks[(ni * 8 + g) * AQS + k8 + q];
                bb[1] = Ks[(ni * 8 + g) * AQS + k8 + q + 4];
                mma_tf32(s[ni], a, bb);
            }
        }

        #pragma unroll
        for (int ni = 0; ni < 8; ni++)
            #pragma unroll
            for (int r = 0; r < 4; r++) s[ni][r] *= 0.125f;
        if (kt == qt) {
            int r0 = qr + g, r1 = qr + g + 8;
            #pragma unroll
            for (int ni = 0; ni < 8; ni++) {
                int c = ni * 8 + (q << 1);
                if (c > r0)     s[ni][0] = NEG;
                if (c + 1 > r0) s[ni][1] = NEG;
                if (c > r1)     s[ni][2] = NEG;
                if (c + 1 > r1) s[ni][3] = NEG;
            }
        }

        float mx0 = NEG, mx1 = NEG;
        #pragma unroll
        for (int ni = 0; ni < 8; ni++) {
            mx0 = fmaxf(mx0, fmaxf(s[ni][0], s[ni][1]));
            mx1 = fmaxf(mx1, fmaxf(s[ni][2], s[ni][3]));
        }
        mx0 = fmaxf(mx0, __shfl_xor_sync(0xffffffffu, mx0, 1));
        mx0 = fmaxf(mx0, __shfl_xor_sync(0xffffffffu, mx0, 2));
        mx1 = fmaxf(mx1, __shfl_xor_sync(0xffffffffu, mx1, 1));
        mx1 = fmaxf(mx1, __shfl_xor_sync(0xffffffffu, mx1, 2));

        float mn0 = fmaxf(mrow0, mx0), mn1 = fmaxf(mrow1, mx1);
        float corr0 = __expf(mrow0 - mn0), corr1 = __expf(mrow1 - mn1);
        float sum0 = 0.0f, sum1 = 0.0f;
        #pragma unroll
        for (int ni = 0; ni < 8; ni++) {
            s[ni][0] = __expf(s[ni][0] - mn0);
            s[ni][1] = __expf(s[ni][1] - mn0);
            s[ni][2] = __expf(s[ni][2] - mn1);
            s[ni][3] = __expf(s[ni][3] - mn1);
            sum0 += s[ni][0] + s[ni][1];
            sum1 += s[ni][2] + s[ni][3];
        }
        sum0 += __shfl_xor_sync(0xffffffffu, sum0, 1);
        sum0 += __shfl_xor_sync(0xffffffffu, sum0, 2);
        sum1 += __shfl_xor_sync(0xffffffffu, sum1, 1);
        sum1 += __shfl_xor_sync(0xffffffffu, sum1, 2);
        lrow0 = lrow0 * corr0 + sum0;
        lrow1 = lrow1 * corr1 + sum1;
        mrow0 = mn0; mrow1 = mn1;
        #pragma unroll
        for (int ni = 0; ni < 8; ni++) {
            O[ni][0] *= corr0; O[ni][1] *= corr0;
            O[ni][2] *= corr1; O[ni][3] *= corr1;
        }

        #pragma unroll
        for (int ni = 0; ni < 8; ni++) {
            int c = ni * 8 + (q << 1);
            uint2 p0, p1;
            p0.x = f32_to_tf32(s[ni][0]); p0.y = f32_to_tf32(s[ni][1]);
            p1.x = f32_to_tf32(s[ni][2]); p1.y = f32_to_tf32(s[ni][3]);
            *(uint2*)&Ps[(qr + g) * AQS + c]     = p0;
            *(uint2*)&Ps[(qr + g + 8) * AQS + c] = p1;
        }
        __syncwarp();

        #pragma unroll
        for (int k8 = 0; k8 < 64; k8 += 8) {
            uint32_t a[4];
            a[0] = Ps[(qr + g) * AQS + k8 + q];
            a[1] = Ps[(qr + g + 8) * AQS + k8 + q];
            a[2] = Ps[(qr + g) * AQS + k8 + q + 4];
            a[3] = Ps[(qr + g + 8) * AQS + k8 + q + 4];
            #pragma unroll
            for (int ni = 0; ni < 8; ni++) {
                uint32_t bb[2];
                bb[0] = Vs[(k8 + q) * AVS + ni * 8 + g];
                bb[1] = Vs[(k8 + q + 4) * AVS + ni * 8 + g];
                mma_tf32(O[ni], a, bb);
            }
        }
    }

    float inv0 = 1.0f / lrow0, inv1 = 1.0f / lrow1;
    int r0 = q0 + qr + g, r1 = r0 + 8;
    float* d0 = g_attn + (size_t)(b * S_LEN + r0) * DMODEL + h * HD;
    float* d1 = g_attn + (size_t)(b * S_LEN + r1) * DMODEL + h * HD;
    #pragma unroll
    for (int ni = 0; ni < 8; ni++) {
        int c = ni * 8 + (q << 1);
        float2 o0, o1;
        o0.x = O[ni][0] * inv0; o0.y = O[ni][1] * inv0;
        o1.x = O[ni][2] * inv1; o1.y = O[ni][3] * inv1;
        *(float2*)&d0[c] = o0;
        *(float2*)&d1[c] = o1;
    }
}

// ---------------------------------------------------------------------------
// kernel_launch: x, w_qkv, b_qkv, w_proj, b_proj
// ---------------------------------------------------------------------------
extern "C" void kernel_launch(void* const* d_in, const int* in_sizes, int n_in,
                              void* d_out, int out_size)
{
    const float* x      = (const float*)d_in[0];
    const float* w_qkv  = (const float*)d_in[1];
    const float* b_qkv  = (const float*)d_in[2];
    const float* w_proj = (const float*)d_in[3];
    const float* b_proj = (const float*)d_in[4];
    float* out = (float*)d_out;

    void *x_h, *wqkv_h, *wproj_h, *qkv, *attn, *attn_h;
    cudaGetSymbolAddress(&x_h, g_x_h);
    cudaGetSymbolAddress(&wqkv_h, g_wqkv_h);
    cudaGetSymbolAddress(&wproj_h, g_wproj_h);
    cudaGetSymbolAddress(&qkv, g_qkv);
    cudaGetSymbolAddress(&attn, g_attn);
    cudaGetSymbolAddress(&attn_h, g_attn_h);

    cudaFuncSetAttribute(f16_gemm_kernel,
                         cudaFuncAttributeMaxDynamicSharedMemorySize,
                         GEMM_SMEM_BYTES);
    cudaFuncSetAttribute(attn_mma_kernel,
                         cudaFuncAttributeMaxDynamicSharedMemorySize,
                         ATTN_SMEM_BYTES);

    // 0) prepass: convert x to fp16; transpose-convert weights to [N][K] fp16
    {
        int n4x = MTOK * DMODEL / 4;
        cvt_f16_kernel<<<(n4x + 255) / 256, 256>>>(
            (const float4*)x, (__half2*)x_h, n4x);
        dim3 tblk(32, 8);
        dim3 tg1(3 * DMODEL / 32, DMODEL / 32);
        transpose_f16_kernel<<<tg1, tblk>>>(w_qkv, (__half*)wqkv_h,
                                            DMODEL, 3 * DMODEL);
        dim3 tg2(DMODEL / 32, DMODEL / 32);
        transpose_f16_kernel<<<tg2, tblk>>>(w_proj, (__half*)wproj_h,
                                            DMODEL, DMODEL);
    }

    // 1) QKV projection (fp16 MMA): [8192,1024] @ [1024,3072] + b
    {
        dim3 grid(3 * DMODEL / GBN, MTOK / GBM);
        f16_gemm_kernel<<<grid, 256, GEMM_SMEM_BYTES>>>(
            (const __half*)x_h, (const __half*)wqkv_h, b_qkv, (float*)qkv,
            MTOK, 3 * DMODEL, DMODEL);
    }

    // 2) causal flash attention on tensor cores (tf32, proven)
    {
        dim3 grid(S_LEN / 64, BATCH * NHEAD);
        attn_mma_kernel<<<grid, 128, ATTN_SMEM_BYTES>>>();
    }

    // 3) convert attention output to fp16, then output projection (fp16 MMA)
    {
        int n4a = MTOK * DMODEL / 4;
        cvt_f16_kernel<<<(n4a + 255) / 256, 256>>>(
            (const float4*)attn, (__half2*)attn_h, n4a);
        dim3 grid(DMODEL / GBN, MTOK / GBM);
        f16_gemm_kernel<<<grid, 256, GEMM_SMEM_BYTES>>>(
            (const __half*)attn_h, (const __half*)wproj_h, b_proj, out,
            MTOK, DMODEL, DMODEL);
    }
}

// round 12
// speedup vs baseline: 1.5461x; 1.1661x over previous
#include <cuda_runtime.h>
#include <cuda_fp16.h>
#include <math.h>
#include <stdint.h>

// Problem shape (fixed by the dataset)
#define BATCH   4
#define S_LEN   2048
#define DMODEL  1024
#define NHEAD   16
#define HD      64
#define MTOK    (BATCH * S_LEN)        // 8192 token rows

// ---------------------------------------------------------------------------
// Scratch (device globals: allocation-free)
// ---------------------------------------------------------------------------
__device__ __align__(16) __half g_x_h[(size_t)MTOK * DMODEL];          // x fp16
__device__ __align__(16) __half g_wqkv_h[(size_t)3 * DMODEL * DMODEL]; // w_qkv^T [N][K]
__device__ __align__(16) __half g_wproj_h[(size_t)DMODEL * DMODEL];    // w_proj^T [N][K]
__device__ __align__(16) float  g_qkv[(size_t)MTOK * 3 * DMODEL];      // fp32 qkv
__device__ __align__(16) __half g_attn_h[(size_t)MTOK * DMODEL];       // attn out fp16

// bit-reinterpret __half2 -> uint32 (no intrinsic exists for this)
__device__ __forceinline__ uint32_t h2u(__half2 h) {
    union { __half2 h; uint32_t u; } c;
    c.h = h;
    return c.u;
}

__device__ __forceinline__ void mma_f16(float* c, const uint32_t* a,
                                        const uint32_t* b) {
    asm volatile(
        "mma.sync.aligned.m16n8k16.row.col.f32.f16.f16.f32 "
        "{%0,%1,%2,%3}, {%4,%5,%6,%7}, {%8,%9}, {%0,%1,%2,%3};"
        : "+f"(c[0]), "+f"(c[1]), "+f"(c[2]), "+f"(c[3])
        : "r"(a[0]), "r"(a[1]), "r"(a[2]), "r"(a[3]), "r"(b[0]), "r"(b[1]));
}

__device__ __forceinline__ void ldmatrix_x4_trans(
    uint32_t& r0, uint32_t& r1, uint32_t& r2, uint32_t& r3, uint32_t addr) {
    asm volatile(
        "ldmatrix.sync.aligned.m8n8.x4.trans.shared.b16 {%0,%1,%2,%3}, [%4];"
        : "=r"(r0), "=r"(r1), "=r"(r2), "=r"(r3) : "r"(addr));
}

__device__ __forceinline__ uint32_t smem_u32(const void* p) {
    uint32_t a;
    asm("{ .reg .u64 t; cvta.to.shared.u64 t, %1; cvt.u32.u64 %0, t; }"
        : "=r"(a) : "l"(p));
    return a;
}
__device__ __forceinline__ void cp_async16(uint32_t dst, const void* src) {
    asm volatile("cp.async.cg.shared.global [%0], [%1], 16;"
                 :: "r"(dst), "l"(src));
}
#define CP_COMMIT()  asm volatile("cp.async.commit_group;" ::: "memory")
#define CP_WAIT1()   asm volatile("cp.async.wait_group 1;" ::: "memory")

// ---------------------------------------------------------------------------
// fp16 tensor-core GEMM (unchanged from round 10 — proven).
// C[M,N] = A[M,K](f16) @ Bt[N,K](f16)^T + bias[N]
// ---------------------------------------------------------------------------
#define GBM 128
#define GBN 256
#define GBK 32
#define KPW 20
#define A_TW (128 * KPW)
#define B_TW (256 * KPW)
#define STG_W (A_TW + B_TW)
#define GEMM_SMEM_BYTES (3 * STG_W * 4)

__global__ __launch_bounds__(256, 1) void f16_gemm_kernel(
    const __half* __restrict__ A, const __half* __restrict__ Bt,
    const float* __restrict__ bias, float* __restrict__ C,
    int M, int N, int K)
{
    extern __shared__ uint32_t smw[];
    const uint32_t smb = smem_u32(smw);

    const int tid  = threadIdx.x;
    const int wid  = tid >> 5;
    const int lane = tid & 31;
    const int g = lane >> 2;
    const int q = lane & 3;

    const int wm = (wid & 1) << 6;
    const int wn = (wid >> 1) << 6;

    const int bm = blockIdx.y * GBM;
    const int bn = blockIdx.x * GBN;
    const int NT = K / GBK;

    const int c_row = tid >> 1;
    const int c_h   = (tid & 1) << 4;
    const int c_w   = (tid & 1) << 3;

    auto issue = [&](int s, int kt) {
        uint32_t sb = smb + (uint32_t)(s * STG_W) * 4;
        const __half* Ar = A + (size_t)(bm + c_row) * K + kt * GBK + c_h;
        uint32_t ad = sb + (uint32_t)(c_row * KPW + c_w) * 4;
        cp_async16(ad, Ar);
        cp_async16(ad + 16, Ar + 8);
        uint32_t bb = sb + (uint32_t)A_TW * 4;
        #pragma unroll
        for (int r = 0; r < 2; r++) {
            int row = c_row + (r << 7);
            const __half* Br = Bt + (size_t)(bn + row) * K + kt * GBK + c_h;
            uint32_t bd = bb + (uint32_t)(row * KPW + c_w) * 4;
            cp_async16(bd, Br);
            cp_async16(bd + 16, Br + 8);
        }
    };

    float acc[4][8][4];
    #pragma unroll
    for (int mi = 0; mi < 4; mi++)
        #pragma unroll
        for (int ni = 0; ni < 8; ni++)
            #pragma unroll
            for (int r = 0; r < 4; r++) acc[mi][ni][r] = 0.0f;

    issue(0, 0); CP_COMMIT();
    issue(1, 1); CP_COMMIT();

    for (int kt = 0; kt < NT; kt++) {
        CP_WAIT1();
        __syncthreads();
        if (kt + 2 < NT) issue((kt + 2) % 3, kt + 2);
        CP_COMMIT();

        const uint32_t* As = smw + (kt % 3) * STG_W;
        const uint32_t* Bs = As + A_TW;

        #pragma unroll
        for (int s16 = 0; s16 < 2; s16++) {
            const int s8 = s16 << 3;
            uint32_t af[4][4], bf[8][2];
            #pragma unroll
            for (int mi = 0; mi < 4; mi++) {
                const uint32_t* ar = As + (wm + (mi << 4) + g) * KPW + s8 + q;
                af[mi][0] = ar[0];
                af[mi][1] = ar[8 * KPW];
                af[mi][2] = ar[4];
                af[mi][3] = ar[8 * KPW + 4];
            }
            #pragma unroll
            for (int ni = 0; ni < 8; ni++) {
                const uint32_t* br = Bs + (wn + (ni << 3) + g) * KPW + s8 + q;
                bf[ni][0] = br[0];
                bf[ni][1] = br[4];
            }
            #pragma unroll
            for (int mi = 0; mi < 4; mi++)
                #pragma unroll
                for (int ni = 0; ni < 8; ni++)
                    mma_f16(acc[mi][ni], af[mi], bf[ni]);
        }
    }

    #pragma unroll
    for (int mi = 0; mi < 4; mi++) {
        int m = bm + wm + (mi << 4) + g;
        #pragma unroll
        for (int ni = 0; ni < 8; ni++) {
            int n = bn + wn + (ni << 3) + (q << 1);
            float2 bb = *(const float2*)&bias[n];
            float2 o0, o1;
            o0.x = acc[mi][ni][0] + bb.x;
            o0.y = acc[mi][ni][1] + bb.y;
            o1.x = acc[mi][ni][2] + bb.x;
            o1.y = acc[mi][ni][3] + bb.y;
            *(float2*)&C[(size_t)m * N + n]       = o0;
            *(float2*)&C[(size_t)(m + 8) * N + n] = o1;
        }
    }
}

// ---------------------------------------------------------------------------
// Prepass kernels (unchanged)
// ---------------------------------------------------------------------------
__global__ void cvt_f16_kernel(const float4* __restrict__ src,
                               __half2* __restrict__ dst, int n4)
{
    int i = blockIdx.x * blockDim.x + threadIdx.x;
    if (i < n4) {
        float4 v = src[i];
        dst[i * 2]     = __floats2half2_rn(v.x, v.y);
        dst[i * 2 + 1] = __floats2half2_rn(v.z, v.w);
    }
}

__global__ void transpose_f16_kernel(const float* __restrict__ src,
                                     __half* __restrict__ dst, int K, int N)
{
    __shared__ __half t[32][33];
    const int n0 = blockIdx.x * 32, k0 = blockIdx.y * 32;
    const int tx = threadIdx.x, ty = threadIdx.y;
    #pragma unroll
    for (int i = ty; i < 32; i += 8)
        t[i][tx] = __float2half_rn(src[(size_t)(k0 + i) * N + n0 + tx]);
    __syncthreads();
    #pragma unroll
    for (int i = ty; i < 32; i += 8)
        dst[(size_t)(n0 + i) * K + k0 + tx] = t[tx][i];
}

// ---------------------------------------------------------------------------
// Flash attention, fp16 mma.sync m16n8k16, causal.
// 64-row q-tile, 4 warps (proven structure). All tiles fp16, stride 36 words
// (72 fp16) per row: fragment banks = 4g+q (conflict-free); ldmatrix rows at
// bank 4r (conflict-free). V consumed via ldmatrix.x4.trans (no transpose).
// smem: Qs, Ks, Vs, Ps each [64][36] words = 36864 B total.
// ---------------------------------------------------------------------------
#define AS 36
#define ATTN_SMEM_BYTES (4 * 64 * AS * 4)

__global__ __launch_bounds__(128) void attn_mma_kernel()
{
    extern __shared__ uint32_t smu[];
    uint32_t* Qs = smu;                 // [64][36] half2-words
    uint32_t* Ks = Qs + 64 * AS;
    uint32_t* Vs = Ks + 64 * AS;
    uint32_t* Ps = Vs + 64 * AS;
    const uint32_t vb = smem_u32(Vs);

    const int tid  = threadIdx.x;
    const int wid  = tid >> 5;
    const int lane = tid & 31;
    const int g = lane >> 2;
    const int q = lane & 3;
    const int l8 = lane & 7;
    const int lt = lane >> 3;

    const int qt = blockIdx.x;
    const int bh = blockIdx.y;
    const int b  = bh >> 4;
    const int h  = bh & (NHEAD - 1);

    const int q0 = qt * 64;
    const int qr = wid << 4;
    const float NEG = -1e30f;

    // stage Q (fp32 -> fp16)
    for (int i = tid; i < 1024; i += 128) {
        int row = i >> 4, c4 = (i & 15) << 2;
        float4 v = *(const float4*)(g_qkv
            + (size_t)(b * S_LEN + q0 + row) * (3 * DMODEL) + h * HD + c4);
        uint2 o;
        o.x = h2u(__floats2half2_rn(v.x, v.y));
        o.y = h2u(__floats2half2_rn(v.z, v.w));
        *(uint2*)&Qs[row * AS + (c4 >> 1)] = o;
    }

    float O[8][4];
    #pragma unroll
    for (int ni = 0; ni < 8; ni++)
        #pragma unroll
        for (int r = 0; r < 4; r++) O[ni][r] = 0.0f;
    float mrow0 = NEG, mrow1 = NEG, lrow0 = 0.0f, lrow1 = 0.0f;

    for (int kt = 0; kt <= qt; kt++) {
        const int k0 = kt * 64;
        __syncthreads();
        // stage K & V (fp32 -> fp16)
        for (int i = tid; i < 1024; i += 128) {
            int row = i >> 4, c4 = (i & 15) << 2;
            const float* base = g_qkv
                + (size_t)(b * S_LEN + k0 + row) * (3 * DMODEL)
                + DMODEL + h * HD + c4;
            float4 kv = *(const float4*)base;
            float4 vv = *(const float4*)(base + DMODEL);
            uint2 ok, ov;
            ok.x = h2u(__floats2half2_rn(kv.x, kv.y));
            ok.y = h2u(__floats2half2_rn(kv.z, kv.w));
            ov.x = h2u(__floats2half2_rn(vv.x, vv.y));
            ov.y = h2u(__floats2half2_rn(vv.z, vv.w));
            *(uint2*)&Ks[row * AS + (c4 >> 1)] = ok;
            *(uint2*)&Vs[row * AS + (c4 >> 1)] = ov;
        }
        __syncthreads();

        // S = Q @ K^T  (warp: 16 x 64, hd=64 -> 4 k16 steps)
        float s[8][4];
        #pragma unroll
        for (int ni = 0; ni < 8; ni++)
            #pragma unroll
            for (int r = 0; r < 4; r++) s[ni][r] = 0.0f;

        #pragma unroll
        for (int ks = 0; ks < 4; ks++) {
            const int s8 = ks << 3;
            uint32_t a[4];
            const uint32_t* ar = Qs + (qr + g) * AS + s8 + q;
            a[0] = ar[0];
            a[1] = ar[8 * AS];
            a[2] = ar[4];
            a[3] = ar[8 * AS + 4];
            #pragma unroll
            for (int ni = 0; ni < 8; ni++) {
                const uint32_t* br = Ks + (ni * 8 + g) * AS + s8 + q;
                uint32_t bb[2] = { br[0], br[4] };
                mma_f16(s[ni], a, bb);
            }
        }

        // scale + causal mask (diagonal tile only)
        #pragma unroll
        for (int ni = 0; ni < 8; ni++)
            #pragma unroll
            for (int r = 0; r < 4; r++) s[ni][r] *= 0.125f;
        if (kt == qt) {
            int r0 = qr + g, r1 = qr + g + 8;
            #pragma unroll
            for (int ni = 0; ni < 8; ni++) {
                int c = ni * 8 + (q << 1);
                if (c > r0)     s[ni][0] = NEG;
                if (c + 1 > r0) s[ni][1] = NEG;
                if (c > r1)     s[ni][2] = NEG;
                if (c + 1 > r1) s[ni][3] = NEG;
            }
        }

        // online softmax
        float mx0 = NEG, mx1 = NEG;
        #pragma unroll
        for (int ni = 0; ni < 8; ni++) {
            mx0 = fmaxf(mx0, fmaxf(s[ni][0], s[ni][1]));
            mx1 = fmaxf(mx1, fmaxf(s[ni][2], s[ni][3]));
        }
        mx0 = fmaxf(mx0, __shfl_xor_sync(0xffffffffu, mx0, 1));
        mx0 = fmaxf(mx0, __shfl_xor_sync(0xffffffffu, mx0, 2));
        mx1 = fmaxf(mx1, __shfl_xor_sync(0xffffffffu, mx1, 1));
        mx1 = fmaxf(mx1, __shfl_xor_sync(0xffffffffu, mx1, 2));

        float mn0 = fmaxf(mrow0, mx0), mn1 = fmaxf(mrow1, mx1);
        float corr0 = __expf(mrow0 - mn0), corr1 = __expf(mrow1 - mn1);
        float sum0 = 0.0f, sum1 = 0.0f;
        #pragma unroll
        for (int ni = 0; ni < 8; ni++) {
            s[ni][0] = __expf(s[ni][0] - mn0);
            s[ni][1] = __expf(s[ni][1] - mn0);
            s[ni][2] = __expf(s[ni][2] - mn1);
            s[ni][3] = __expf(s[ni][3] - mn1);
            sum0 += s[ni][0] + s[ni][1];
            sum1 += s[ni][2] + s[ni][3];
        }
        sum0 += __shfl_xor_sync(0xffffffffu, sum0, 1);
        sum0 += __shfl_xor_sync(0xffffffffu, sum0, 2);
        sum1 += __shfl_xor_sync(0xffffffffu, sum1, 1);
        sum1 += __shfl_xor_sync(0xffffffffu, sum1, 2);
        lrow0 = lrow0 * corr0 + sum0;
        lrow1 = lrow1 * corr1 + sum1;
        mrow0 = mn0; mrow1 = mn1;
        #pragma unroll
        for (int ni = 0; ni < 8; ni++) {
            O[ni][0] *= corr0; O[ni][1] *= corr0;
            O[ni][2] *= corr1; O[ni][3] *= corr1;
        }

        // P -> smem fp16 (warp-private stripe)
        #pragma unroll
        for (int ni = 0; ni < 8; ni++) {
            Ps[(qr + g) * AS + ni * 4 + q] =
                h2u(__floats2half2_rn(s[ni][0], s[ni][1]));
            Ps[(qr + g + 8) * AS + ni * 4 + q] =
                h2u(__floats2half2_rn(s[ni][2], s[ni][3]));
        }
        __syncwarp();

        // O += P @ V : A-frag from Ps, B-frag from Vs via ldmatrix.trans
        #pragma unroll
        for (int ks = 0; ks < 4; ks++) {
            const int s8 = ks << 3;
            uint32_t a[4];
            const uint32_t* ar = Ps + (qr + g) * AS + s8 + q;
            a[0] = ar[0];
            a[1] = ar[8 * AS];
            a[2] = ar[4];
            a[3] = ar[8 * AS + 4];

            uint32_t vb0[8], vb1[8];
            #pragma unroll
            for (int m = 0; m < 4; m++) {
                // lane l: tile lt = l>>3, row l8 = l&7
                // tile: key half = lt&1, n col pair = 2m + (lt>>1)
                uint32_t addr = vb + (uint32_t)(
                    (((ks << 4) + ((lt & 1) << 3) + l8) * AS
                     + ((m << 1) + (lt >> 1)) * 4) * 4);
                ldmatrix_x4_trans(vb0[2 * m], vb1[2 * m],
                                  vb0[2 * m + 1], vb1[2 * m + 1], addr);
            }
            #pragma unroll
            for (int ni = 0; ni < 8; ni++) {
                uint32_t bb[2] = { vb0[ni], vb1[ni] };
                mma_f16(O[ni], a, bb);
            }
        }
    }

    // normalize + store fp16 (proj GEMM consumes directly)
    float inv0 = 1.0f / lrow0, inv1 = 1.0f / lrow1;
    int r0 = q0 + qr + g, r1 = r0 + 8;
    __half* d0 = g_attn_h + (size_t)(b * S_LEN + r0) * DMODEL + h * HD;
    __half* d1 = g_attn_h + (size_t)(b * S_LEN + r1) * DMODEL + h * HD;
    #pragma unroll
    for (int ni = 0; ni < 8; ni++) {
        int c = ni * 8 + (q << 1);
        *(__half2*)&d0[c] = __floats2half2_rn(O[ni][0] * inv0, O[ni][1] * inv0);
        *(__half2*)&d1[c] = __floats2half2_rn(O[ni][2] * inv1, O[ni][3] * inv1);
    }
}

// ---------------------------------------------------------------------------
// kernel_launch: x, w_qkv, b_qkv, w_proj, b_proj
// ---------------------------------------------------------------------------
extern "C" void kernel_launch(void* const* d_in, const int* in_sizes, int n_in,
                              void* d_out, int out_size)
{
    const float* x      = (const float*)d_in[0];
    const float* w_qkv  = (const float*)d_in[1];
    const float* b_qkv  = (const float*)d_in[2];
    const float* w_proj = (const float*)d_in[3];
    const float* b_proj = (const float*)d_in[4];
    float* out = (float*)d_out;

    void *x_h, *wqkv_h, *wproj_h, *qkv, *attn_h;
    cudaGetSymbolAddress(&x_h, g_x_h);
    cudaGetSymbolAddress(&wqkv_h, g_wqkv_h);
    cudaGetSymbolAddress(&wproj_h, g_wproj_h);
    cudaGetSymbolAddress(&qkv, g_qkv);
    cudaGetSymbolAddress(&attn_h, g_attn_h);

    cudaFuncSetAttribute(f16_gemm_kernel,
                         cudaFuncAttributeMaxDynamicSharedMemorySize,
                         GEMM_SMEM_BYTES);
    cudaFuncSetAttribute(attn_mma_kernel,
                         cudaFuncAttributeMaxDynamicSharedMemorySize,
                         ATTN_SMEM_BYTES);

    // 0) prepass: x -> fp16; weights transpose-convert to [N][K] fp16
    {
        int n4x = MTOK * DMODEL / 4;
        cvt_f16_kernel<<<(n4x + 255) / 256, 256>>>(
            (const float4*)x, (__half2*)x_h, n4x);
        dim3 tblk(32, 8);
        dim3 tg1(3 * DMODEL / 32, DMODEL / 32);
        transpose_f16_kernel<<<tg1, tblk>>>(w_qkv, (__half*)wqkv_h,
                                            DMODEL, 3 * DMODEL);
        dim3 tg2(DMODEL / 32, DMODEL / 32);
        transpose_f16_kernel<<<tg2, tblk>>>(w_proj, (__half*)wproj_h,
                                            DMODEL, DMODEL);
    }

    // 1) QKV projection (fp16 MMA)
    {
        dim3 grid(3 * DMODEL / GBN, MTOK / GBM);
        f16_gemm_kernel<<<grid, 256, GEMM_SMEM_BYTES>>>(
            (const __half*)x_h, (const __half*)wqkv_h, b_qkv, (float*)qkv,
            MTOK, 3 * DMODEL, DMODEL);
    }

    // 2) causal flash attention (fp16 MMA, ldmatrix.trans V)
    {
        dim3 grid(S_LEN / 64, BATCH * NHEAD);
        attn_mma_kernel<<<grid, 128, ATTN_SMEM_BYTES>>>();
    }

    // 3) output projection (fp16 MMA) straight from fp16 attention output
    {
        dim3 grid(DMODEL / GBN, MTOK / GBM);
        f16_gemm_kernel<<<grid, 256, GEMM_SMEM_BYTES>>>(
            (const __half*)attn_h, (const __half*)wproj_h, b_proj, out,
            MTOK, DMODEL, DMODEL);
    }
}

// round 13
// speedup vs baseline: 1.7504x; 1.1321x over previous
#include <cuda_runtime.h>
#include <cuda_fp16.h>
#include <math.h>
#include <stdint.h>

// Problem shape (fixed by the dataset)
#define BATCH   4
#define S_LEN   2048
#define DMODEL  1024
#define NHEAD   16
#define HD      64
#define MTOK    (BATCH * S_LEN)        // 8192 token rows

// ---------------------------------------------------------------------------
// Scratch (device globals: allocation-free)
// ---------------------------------------------------------------------------
__device__ __align__(16) __half g_x_h[(size_t)MTOK * DMODEL];          // x fp16
__device__ __align__(16) __half g_wqkv_h[(size_t)3 * DMODEL * DMODEL]; // w_qkv^T [N][K]
__device__ __align__(16) __half g_wproj_h[(size_t)DMODEL * DMODEL];    // w_proj^T [N][K]
__device__ __align__(16) __half g_qkv_h[(size_t)MTOK * 3 * DMODEL];    // fp16 qkv
__device__ __align__(16) __half g_attn_h[(size_t)MTOK * DMODEL];       // attn out fp16

// bit-reinterpret __half2 -> uint32
__device__ __forceinline__ uint32_t h2u(__half2 h) {
    union { __half2 h; uint32_t u; } c;
    c.h = h;
    return c.u;
}

__device__ __forceinline__ void mma_f16(float* c, const uint32_t* a,
                                        const uint32_t* b) {
    asm volatile(
        "mma.sync.aligned.m16n8k16.row.col.f32.f16.f16.f32 "
        "{%0,%1,%2,%3}, {%4,%5,%6,%7}, {%8,%9}, {%0,%1,%2,%3};"
        : "+f"(c[0]), "+f"(c[1]), "+f"(c[2]), "+f"(c[3])
        : "r"(a[0]), "r"(a[1]), "r"(a[2]), "r"(a[3]), "r"(b[0]), "r"(b[1]));
}

__device__ __forceinline__ void ldmatrix_x4_trans(
    uint32_t& r0, uint32_t& r1, uint32_t& r2, uint32_t& r3, uint32_t addr) {
    asm volatile(
        "ldmatrix.sync.aligned.m8n8.x4.trans.shared.b16 {%0,%1,%2,%3}, [%4];"
        : "=r"(r0), "=r"(r1), "=r"(r2), "=r"(r3) : "r"(addr));
}

__device__ __forceinline__ uint32_t smem_u32(const void* p) {
    uint32_t a;
    asm("{ .reg .u64 t; cvta.to.shared.u64 t, %1; cvt.u32.u64 %0, t; }"
        : "=r"(a) : "l"(p));
    return a;
}
__device__ __forceinline__ void cp_async16(uint32_t dst, const void* src) {
    asm volatile("cp.async.cg.shared.global [%0], [%1], 16;"
                 :: "r"(dst), "l"(src));
}
#define CP_COMMIT()  asm volatile("cp.async.commit_group;" ::: "memory")
#define CP_WAIT1()   asm volatile("cp.async.wait_group 1;" ::: "memory")

// ---------------------------------------------------------------------------
// fp16 tensor-core GEMM (round-10 proven structure).
// C[M,N] = A[M,K](f16) @ Bt[N,K](f16)^T + bias[N]
// Output: fp32 to Cf (if Ch == nullptr) or fp16 to Ch.
// ---------------------------------------------------------------------------
#define GBM 128
#define GBN 256
#define GBK 32
#define KPW 20
#define A_TW (128 * KPW)
#define B_TW (256 * KPW)
#define STG_W (A_TW + B_TW)
#define GEMM_SMEM_BYTES (3 * STG_W * 4)

__global__ __launch_bounds__(256, 1) void f16_gemm_kernel(
    const __half* __restrict__ A, const __half* __restrict__ Bt,
    const float* __restrict__ bias, float* __restrict__ Cf,
    __half* __restrict__ Ch, int M, int N, int K)
{
    extern __shared__ uint32_t smw[];
    const uint32_t smb = smem_u32(smw);

    const int tid  = threadIdx.x;
    const int wid  = tid >> 5;
    const int lane = tid & 31;
    const int g = lane >> 2;
    const int q = lane & 3;

    const int wm = (wid & 1) << 6;
    const int wn = (wid >> 1) << 6;

    const int bm = blockIdx.y * GBM;
    const int bn = blockIdx.x * GBN;
    const int NT = K / GBK;

    const int c_row = tid >> 1;
    const int c_h   = (tid & 1) << 4;
    const int c_w   = (tid & 1) << 3;

    auto issue = [&](int s, int kt) {
        uint32_t sb = smb + (uint32_t)(s * STG_W) * 4;
        const __half* Ar = A + (size_t)(bm + c_row) * K + kt * GBK + c_h;
        uint32_t ad = sb + (uint32_t)(c_row * KPW + c_w) * 4;
        cp_async16(ad, Ar);
        cp_async16(ad + 16, Ar + 8);
        uint32_t bb = sb + (uint32_t)A_TW * 4;
        #pragma unroll
        for (int r = 0; r < 2; r++) {
            int row = c_row + (r << 7);
            const __half* Br = Bt + (size_t)(bn + row) * K + kt * GBK + c_h;
            uint32_t bd = bb + (uint32_t)(row * KPW + c_w) * 4;
            cp_async16(bd, Br);
            cp_async16(bd + 16, Br + 8);
        }
    };

    float acc[4][8][4];
    #pragma unroll
    for (int mi = 0; mi < 4; mi++)
        #pragma unroll
        for (int ni = 0; ni < 8; ni++)
            #pragma unroll
            for (int r = 0; r < 4; r++) acc[mi][ni][r] = 0.0f;

    issue(0, 0); CP_COMMIT();
    issue(1, 1); CP_COMMIT();

    for (int kt = 0; kt < NT; kt++) {
        CP_WAIT1();
        __syncthreads();
        if (kt + 2 < NT) issue((kt + 2) % 3, kt + 2);
        CP_COMMIT();

        const uint32_t* As = smw + (kt % 3) * STG_W;
        const uint32_t* Bs = As + A_TW;

        #pragma unroll
        for (int s16 = 0; s16 < 2; s16++) {
            const int s8 = s16 << 3;
            uint32_t af[4][4], bf[8][2];
            #pragma unroll
            for (int mi = 0; mi < 4; mi++) {
                const uint32_t* ar = As + (wm + (mi << 4) + g) * KPW + s8 + q;
                af[mi][0] = ar[0];
                af[mi][1] = ar[8 * KPW];
                af[mi][2] = ar[4];
                af[mi][3] = ar[8 * KPW + 4];
            }
            #pragma unroll
            for (int ni = 0; ni < 8; ni++) {
                const uint32_t* br = Bs + (wn + (ni << 3) + g) * KPW + s8 + q;
                bf[ni][0] = br[0];
                bf[ni][1] = br[4];
            }
            #pragma unroll
            for (int mi = 0; mi < 4; mi++)
                #pragma unroll
                for (int ni = 0; ni < 8; ni++)
                    mma_f16(acc[mi][ni], af[mi], bf[ni]);
        }
    }

    // epilogue: bias add in fp32, then fp32 or fp16 store
    #pragma unroll
    for (int mi = 0; mi < 4; mi++) {
        int m = bm + wm + (mi << 4) + g;
        #pragma unroll
        for (int ni = 0; ni < 8; ni++) {
            int n = bn + wn + (ni << 3) + (q << 1);
            float2 bb = *(const float2*)&bias[n];
            float v00 = acc[mi][ni][0] + bb.x;
            float v01 = acc[mi][ni][1] + bb.y;
            float v10 = acc[mi][ni][2] + bb.x;
            float v11 = acc[mi][ni][3] + bb.y;
            if (Ch) {
                *(__half2*)&Ch[(size_t)m * N + n]       = __floats2half2_rn(v00, v01);
                *(__half2*)&Ch[(size_t)(m + 8) * N + n] = __floats2half2_rn(v10, v11);
            } else {
                *(float2*)&Cf[(size_t)m * N + n]       = make_float2(v00, v01);
                *(float2*)&Cf[(size_t)(m + 8) * N + n] = make_float2(v10, v11);
            }
        }
    }
}

// ---------------------------------------------------------------------------
// Prepass kernels (unchanged)
// ---------------------------------------------------------------------------
__global__ void cvt_f16_kernel(const float4* __restrict__ src,
                               __half2* __restrict__ dst, int n4)
{
    int i = blockIdx.x * blockDim.x + threadIdx.x;
    if (i < n4) {
        float4 v = src[i];
        dst[i * 2]     = __floats2half2_rn(v.x, v.y);
        dst[i * 2 + 1] = __floats2half2_rn(v.z, v.w);
    }
}

__global__ void transpose_f16_kernel(const float* __restrict__ src,
                                     __half* __restrict__ dst, int K, int N)
{
    __shared__ __half t[32][33];
    const int n0 = blockIdx.x * 32, k0 = blockIdx.y * 32;
    const int tx = threadIdx.x, ty = threadIdx.y;
    #pragma unroll
    for (int i = ty; i < 32; i += 8)
        t[i][tx] = __float2half_rn(src[(size_t)(k0 + i) * N + n0 + tx]);
    __syncthreads();
    #pragma unroll
    for (int i = ty; i < 32; i += 8)
        dst[(size_t)(n0 + i) * K + k0 + tx] = t[tx][i];
}

// ---------------------------------------------------------------------------
// Flash attention, fp16 mma.sync m16n8k16, causal. (round-12 proven, except
// staging now copies fp16 qkv directly — no conversions.)
// 64-row q-tile, 4 warps. smem tiles [64][36] words each.
// ---------------------------------------------------------------------------
#define AS 36
#define ATTN_SMEM_BYTES (4 * 64 * AS * 4)

__global__ __launch_bounds__(128) void attn_mma_kernel()
{
    extern __shared__ uint32_t smu[];
    uint32_t* Qs = smu;                 // [64][36] half2-words
    uint32_t* Ks = Qs + 64 * AS;
    uint32_t* Vs = Ks + 64 * AS;
    uint32_t* Ps = Vs + 64 * AS;
    const uint32_t vb = smem_u32(Vs);

    const int tid  = threadIdx.x;
    const int wid  = tid >> 5;
    const int lane = tid & 31;
    const int g = lane >> 2;
    const int q = lane & 3;
    const int l8 = lane & 7;
    const int lt = lane >> 3;

    const int qt = blockIdx.x;
    const int bh = blockIdx.y;
    const int b  = bh >> 4;
    const int h  = bh & (NHEAD - 1);

    const int q0 = qt * 64;
    const int qr = wid << 4;
    const float NEG = -1e30f;

    // stage Q: fp16 copy (uint2 = 4 halves)
    for (int i = tid; i < 1024; i += 128) {
        int row = i >> 4, c4 = (i & 15) << 2;
        uint2 v = *(const uint2*)(g_qkv_h
            + (size_t)(b * S_LEN + q0 + row) * (3 * DMODEL) + h * HD + c4);
        *(uint2*)&Qs[row * AS + (c4 >> 1)] = v;
    }

    float O[8][4];
    #pragma unroll
    for (int ni = 0; ni < 8; ni++)
        #pragma unroll
        for (int r = 0; r < 4; r++) O[ni][r] = 0.0f;
    float mrow0 = NEG, mrow1 = NEG, lrow0 = 0.0f, lrow1 = 0.0f;

    for (int kt = 0; kt <= qt; kt++) {
        const int k0 = kt * 64;
        __syncthreads();
        // stage K & V: fp16 copies
        for (int i = tid; i < 1024; i += 128) {
            int row = i >> 4, c4 = (i & 15) << 2;
            const __half* base = g_qkv_h
                + (size_t)(b * S_LEN + k0 + row) * (3 * DMODEL)
                + DMODEL + h * HD + c4;
            uint2 kv = *(const uint2*)base;
            uint2 vv = *(const uint2*)(base + DMODEL);
            *(uint2*)&Ks[row * AS + (c4 >> 1)] = kv;
            *(uint2*)&Vs[row * AS + (c4 >> 1)] = vv;
        }
        __syncthreads();

        // S = Q @ K^T  (warp: 16 x 64, hd=64 -> 4 k16 steps)
        float s[8][4];
        #pragma unroll
        for (int ni = 0; ni < 8; ni++)
            #pragma unroll
            for (int r = 0; r < 4; r++) s[ni][r] = 0.0f;

        #pragma unroll
        for (int ks = 0; ks < 4; ks++) {
            const int s8 = ks << 3;
            uint32_t a[4];
            const uint32_t* ar = Qs + (qr + g) * AS + s8 + q;
            a[0] = ar[0];
            a[1] = ar[8 * AS];
            a[2] = ar[4];
            a[3] = ar[8 * AS + 4];
            #pragma unroll
            for (int ni = 0; ni < 8; ni++) {
                const uint32_t* br = Ks + (ni * 8 + g) * AS + s8 + q;
                uint32_t bb[2] = { br[0], br[4] };
                mma_f16(s[ni], a, bb);
            }
        }

        // scale + causal mask (diagonal tile only)
        #pragma unroll
        for (int ni = 0; ni < 8; ni++)
            #pragma unroll
            for (int r = 0; r < 4; r++) s[ni][r] *= 0.125f;
        if (kt == qt) {
            int r0 = qr + g, r1 = qr + g + 8;
            #pragma unroll
            for (int ni = 0; ni < 8; ni++) {
                int c = ni * 8 + (q << 1);
                if (c > r0)     s[ni][0] = NEG;
                if (c + 1 > r0) s[ni][1] = NEG;
                if (c > r1)     s[ni][2] = NEG;
                if (c + 1 > r1) s[ni][3] = NEG;
            }
        }

        // online softmax
        float mx0 = NEG, mx1 = NEG;
        #pragma unroll
        for (int ni = 0; ni < 8; ni++) {
            mx0 = fmaxf(mx0, fmaxf(s[ni][0], s[ni][1]));
            mx1 = fmaxf(mx1, fmaxf(s[ni][2], s[ni][3]));
        }
        mx0 = fmaxf(mx0, __shfl_xor_sync(0xffffffffu, mx0, 1));
        mx0 = fmaxf(mx0, __shfl_xor_sync(0xffffffffu, mx0, 2));
        mx1 = fmaxf(mx1, __shfl_xor_sync(0xffffffffu, mx1, 1));
        mx1 = fmaxf(mx1, __shfl_xor_sync(0xffffffffu, mx1, 2));

        float mn0 = fmaxf(mrow0, mx0), mn1 = fmaxf(mrow1, mx1);
        float corr0 = __expf(mrow0 - mn0), corr1 = __expf(mrow1 - mn1);
        float sum0 = 0.0f, sum1 = 0.0f;
        #pragma unroll
        for (int ni = 0; ni < 8; ni++) {
            s[ni][0] = __expf(s[ni][0] - mn0);
            s[ni][1] = __expf(s[ni][1] - mn0);
            s[ni][2] = __expf(s[ni][2] - mn1);
            s[ni][3] = __expf(s[ni][3] - mn1);
            sum0 += s[ni][0] + s[ni][1];
            sum1 += s[ni][2] + s[ni][3];
        }
        sum0 += __shfl_xor_sync(0xffffffffu, sum0, 1);
        sum0 += __shfl_xor_sync(0xffffffffu, sum0, 2);
        sum1 += __shfl_xor_sync(0xffffffffu, sum1, 1);
        sum1 += __shfl_xor_sync(0xffffffffu, sum1, 2);
        lrow0 = lrow0 * corr0 + sum0;
        lrow1 = lrow1 * corr1 + sum1;
        mrow0 = mn0; mrow1 = mn1;
        #pragma unroll
        for (int ni = 0; ni < 8; ni++) {
            O[ni][0] *= corr0; O[ni][1] *= corr0;
            O[ni][2] *= corr1; O[ni][3] *= corr1;
        }

        // P -> smem fp16 (warp-private stripe)
        #pragma unroll
        for (int ni = 0; ni < 8; ni++) {
            Ps[(qr + g) * AS + ni * 4 + q] =
                h2u(__floats2half2_rn(s[ni][0], s[ni][1]));
            Ps[(qr + g + 8) * AS + ni * 4 + q] =
                h2u(__floats2half2_rn(s[ni][2], s[ni][3]));
        }
        __syncwarp();

        // O += P @ V : A-frag from Ps, B-frag from Vs via ldmatrix.trans
        #pragma unroll
        for (int ks = 0; ks < 4; ks++) {
            const int s8 = ks << 3;
            uint32_t a[4];
            const uint32_t* ar = Ps + (qr + g) * AS + s8 + q;
            a[0] = ar[0];
            a[1] = ar[8 * AS];
            a[2] = ar[4];
            a[3] = ar[8 * AS + 4];

            uint32_t vb0[8], vb1[8];
            #pragma unroll
            for (int m = 0; m < 4; m++) {
                uint32_t addr = vb + (uint32_t)(
                    (((ks << 4) + ((lt & 1) << 3) + l8) * AS
                     + ((m << 1) + (lt >> 1)) * 4) * 4);
                ldmatrix_x4_trans(vb0[2 * m], vb1[2 * m],
                                  vb0[2 * m + 1], vb1[2 * m + 1], addr);
            }
            #pragma unroll
            for (int ni = 0; ni < 8; ni++) {
                uint32_t bb[2] = { vb0[ni], vb1[ni] };
                mma_f16(O[ni], a, bb);
            }
        }
    }

    // normalize + store fp16 (proj GEMM consumes directly)
    float inv0 = 1.0f / lrow0, inv1 = 1.0f / lrow1;
    int r0 = q0 + qr + g, r1 = r0 + 8;
    __half* d0 = g_attn_h + (size_t)(b * S_LEN + r0) * DMODEL + h * HD;
    __half* d1 = g_attn_h + (size_t)(b * S_LEN + r1) * DMODEL + h * HD;
    #pragma unroll
    for (int ni = 0; ni < 8; ni++) {
        int c = ni * 8 + (q << 1);
        *(__half2*)&d0[c] = __floats2half2_rn(O[ni][0] * inv0, O[ni][1] * inv0);
        *(__half2*)&d1[c] = __floats2half2_rn(O[ni][2] * inv1, O[ni][3] * inv1);
    }
}

// ---------------------------------------------------------------------------
// kernel_launch: x, w_qkv, b_qkv, w_proj, b_proj
// ---------------------------------------------------------------------------
extern "C" void kernel_launch(void* const* d_in, const int* in_sizes, int n_in,
                              void* d_out, int out_size)
{
    const float* x      = (const float*)d_in[0];
    const float* w_qkv  = (const float*)d_in[1];
    const float* b_qkv  = (const float*)d_in[2];
    const float* w_proj = (const float*)d_in[3];
    const float* b_proj = (const float*)d_in[4];
    float* out = (float*)d_out;

    void *x_h, *wqkv_h, *wproj_h, *qkv_h, *attn_h;
    cudaGetSymbolAddress(&x_h, g_x_h);
    cudaGetSymbolAddress(&wqkv_h, g_wqkv_h);
    cudaGetSymbolAddress(&wproj_h, g_wproj_h);
    cudaGetSymbolAddress(&qkv_h, g_qkv_h);
    cudaGetSymbolAddress(&attn_h, g_attn_h);

    cudaFuncSetAttribute(f16_gemm_kernel,
                         cudaFuncAttributeMaxDynamicSharedMemorySize,
                         GEMM_SMEM_BYTES);
    cudaFuncSetAttribute(attn_mma_kernel,
                         cudaFuncAttributeMaxDynamicSharedMemorySize,
                         ATTN_SMEM_BYTES);

    // 0) prepass: x -> fp16; weights transpose-convert to [N][K] fp16
    {
        int n4x = MTOK * DMODEL / 4;
        cvt_f16_kernel<<<(n4x + 255) / 256, 256>>>(
            (const float4*)x, (__half2*)x_h, n4x);
        dim3 tblk(32, 8);
        dim3 tg1(3 * DMODEL / 32, DMODEL / 32);
        transpose_f16_kernel<<<tg1, tblk>>>(w_qkv, (__half*)wqkv_h,
                                            DMODEL, 3 * DMODEL);
        dim3 tg2(DMODEL / 32, DMODEL / 32);
        transpose_f16_kernel<<<tg2, tblk>>>(w_proj, (__half*)wproj_h,
                                            DMODEL, DMODEL);
    }

    // 1) QKV projection (fp16 MMA, fp16 output)
    {
        dim3 grid(3 * DMODEL / GBN, MTOK / GBM);
        f16_gemm_kernel<<<grid, 256, GEMM_SMEM_BYTES>>>(
            (const __half*)x_h, (const __half*)wqkv_h, b_qkv,
            nullptr, (__half*)qkv_h, MTOK, 3 * DMODEL, DMODEL);
    }

    // 2) causal flash attention (fp16 MMA, fp16 staging)
    {
        dim3 grid(S_LEN / 64, BATCH * NHEAD);
        attn_mma_kernel<<<grid, 128, ATTN_SMEM_BYTES>>>();
    }

    // 3) output projection (fp16 MMA, fp32 output)
    {
        dim3 grid(DMODEL / GBN, MTOK / GBM);
        f16_gemm_kernel<<<grid, 256, GEMM_SMEM_BYTES>>>(
            (const __half*)attn_h, (const __half*)wproj_h, b_proj,
            out, nullptr, MTOK, DMODEL, DMODEL);
    }
}

// round 14
// speedup vs baseline: 1.8080x; 1.0329x over previous
#include <cuda_runtime.h>
#include <cuda_fp16.h>
#include <math.h>
#include <stdint.h>

// Problem shape (fixed by the dataset)
#define BATCH   4
#define S_LEN   2048
#define DMODEL  1024
#define NHEAD   16
#define HD      64
#define MTOK    (BATCH * S_LEN)        // 8192 token rows

// ---------------------------------------------------------------------------
// Scratch (device globals: allocation-free)
// ---------------------------------------------------------------------------
__device__ __align__(16) __half g_x_h[(size_t)MTOK * DMODEL];          // x fp16
__device__ __align__(16) __half g_wqkv_h[(size_t)3 * DMODEL * DMODEL]; // w_qkv^T [N][K]
__device__ __align__(16) __half g_wproj_h[(size_t)DMODEL * DMODEL];    // w_proj^T [N][K]
__device__ __align__(16) __half g_qkv_h[(size_t)MTOK * 3 * DMODEL];    // fp16 qkv
__device__ __align__(16) __half g_attn_h[(size_t)MTOK * DMODEL];       // attn out fp16

// bit-reinterpret __half2 -> uint32
__device__ __forceinline__ uint32_t h2u(__half2 h) {
    union { __half2 h; uint32_t u; } c;
    c.h = h;
    return c.u;
}

__device__ __forceinline__ void mma_f16(float* c, const uint32_t* a,
                                        const uint32_t* b) {
    asm volatile(
        "mma.sync.aligned.m16n8k16.row.col.f32.f16.f16.f32 "
        "{%0,%1,%2,%3}, {%4,%5,%6,%7}, {%8,%9}, {%0,%1,%2,%3};"
        : "+f"(c[0]), "+f"(c[1]), "+f"(c[2]), "+f"(c[3])
        : "r"(a[0]), "r"(a[1]), "r"(a[2]), "r"(a[3]), "r"(b[0]), "r"(b[1]));
}

__device__ __forceinline__ void ldmatrix_x4(
    uint32_t& r0, uint32_t& r1, uint32_t& r2, uint32_t& r3, uint32_t addr) {
    asm volatile(
        "ldmatrix.sync.aligned.m8n8.x4.shared.b16 {%0,%1,%2,%3}, [%4];"
        : "=r"(r0), "=r"(r1), "=r"(r2), "=r"(r3) : "r"(addr));
}

__device__ __forceinline__ void ldmatrix_x4_trans(
    uint32_t& r0, uint32_t& r1, uint32_t& r2, uint32_t& r3, uint32_t addr) {
    asm volatile(
        "ldmatrix.sync.aligned.m8n8.x4.trans.shared.b16 {%0,%1,%2,%3}, [%4];"
        : "=r"(r0), "=r"(r1), "=r"(r2), "=r"(r3) : "r"(addr));
}

__device__ __forceinline__ uint32_t smem_u32(const void* p) {
    uint32_t a;
    asm("{ .reg .u64 t; cvta.to.shared.u64 t, %1; cvt.u32.u64 %0, t; }"
        : "=r"(a) : "l"(p));
    return a;
}
__device__ __forceinline__ void cp_async16(uint32_t dst, const void* src) {
    asm volatile("cp.async.cg.shared.global [%0], [%1], 16;"
                 :: "r"(dst), "l"(src));
}
#define CP_COMMIT()  asm volatile("cp.async.commit_group;" ::: "memory")
#define CP_WAIT1()   asm volatile("cp.async.wait_group 1;" ::: "memory")

// ---------------------------------------------------------------------------
// fp16 tensor-core GEMM: C[M,N] = A[M,K](f16) @ Bt[N,K](f16)^T + bias[N]
// Block 128x256, BK=32, 256 threads, 8 warps (2m x 4n), warp tile 64x64.
// 3-stage cp.async pipeline. Fragment loads via ldmatrix.x4 (non-trans):
// both A and B are [outer][k] with k contiguous; row stride 20 words makes
// every 8-address ldmatrix group hit all 32 banks (20r mod 32 bijective).
// Output: fp32 to Cf (if Ch == nullptr) or fp16 to Ch.
// ---------------------------------------------------------------------------
#define GBM 128
#define GBN 256
#define GBK 32
#define KPW 20
#define A_TW (128 * KPW)
#define B_TW (256 * KPW)
#define STG_W (A_TW + B_TW)
#define GEMM_SMEM_BYTES (3 * STG_W * 4)

__global__ __launch_bounds__(256, 1) void f16_gemm_kernel(
    const __half* __restrict__ A, const __half* __restrict__ Bt,
    const float* __restrict__ bias, float* __restrict__ Cf,
    __half* __restrict__ Ch, int M, int N, int K)
{
    extern __shared__ uint32_t smw[];
    const uint32_t smb = smem_u32(smw);

    const int tid  = threadIdx.x;
    const int wid  = tid >> 5;
    const int lane = tid & 31;
    const int g = lane >> 2;
    const int q = lane & 3;
    const int r8 = lane & 7;          // row within ldmatrix 8-group
    const int g4 = lane >> 3;         // ldmatrix address group 0..3

    const int wm = (wid & 1) << 6;
    const int wn = (wid >> 1) << 6;

    const int bm = blockIdx.y * GBM;
    const int bn = blockIdx.x * GBN;
    const int NT = K / GBK;

    const int c_row = tid >> 1;
    const int c_h   = (tid & 1) << 4;
    const int c_w   = (tid & 1) << 3;

    auto issue = [&](int s, int kt) {
        uint32_t sb = smb + (uint32_t)(s * STG_W) * 4;
        const __half* Ar = A + (size_t)(bm + c_row) * K + kt * GBK + c_h;
        uint32_t ad = sb + (uint32_t)(c_row * KPW + c_w) * 4;
        cp_async16(ad, Ar);
        cp_async16(ad + 16, Ar + 8);
        uint32_t bb = sb + (uint32_t)A_TW * 4;
        #pragma unroll
        for (int r = 0; r < 2; r++) {
            int row = c_row + (r << 7);
            const __half* Br = Bt + (size_t)(bn + row) * K + kt * GBK + c_h;
            uint32_t bd = bb + (uint32_t)(row * KPW + c_w) * 4;
            cp_async16(bd, Br);
            cp_async16(bd + 16, Br + 8);
        }
    };

    float acc[4][8][4];
    #pragma unroll
    for (int mi = 0; mi < 4; mi++)
        #pragma unroll
        for (int ni = 0; ni < 8; ni++)
            #pragma unroll
            for (int r = 0; r < 4; r++) acc[mi][ni][r] = 0.0f;

    issue(0, 0); CP_COMMIT();
    issue(1, 1); CP_COMMIT();

    for (int kt = 0; kt < NT; kt++) {
        CP_WAIT1();
        __syncthreads();
        if (kt + 2 < NT) issue((kt + 2) % 3, kt + 2);
        CP_COMMIT();

        const uint32_t As_b = smb + (uint32_t)((kt % 3) * STG_W) * 4;
        const uint32_t Bs_b = As_b + (uint32_t)A_TW * 4;

        #pragma unroll
        for (int s16 = 0; s16 < 2; s16++) {
            const int s8 = s16 << 3;                 // k word offset
            uint32_t af[4][4], bf[8][2];

            // A fragments: per mi one ldmatrix.x4
            // groups: 0 -> m[0:8) k-lo, 1 -> m[8:16) k-lo,
            //         2 -> m[0:8) k-hi(+16B), 3 -> m[8:16) k-hi
            #pragma unroll
            for (int mi = 0; mi < 4; mi++) {
                int row = wm + (mi << 4) + ((g4 & 1) << 3) + r8;
                uint32_t addr = As_b
                    + (uint32_t)(row * KPW + s8) * 4 + ((g4 >> 1) << 4);
                ldmatrix_x4(af[mi][0], af[mi][1], af[mi][2], af[mi][3], addr);
            }

            // B fragments: per pair (2*nj, 2*nj+1) one ldmatrix.x4
            // groups: 0 -> n[8nj..) k-lo, 1 -> same rows k-hi,
            //         2 -> n[8nj+8..) k-lo, 3 -> those rows k-hi
            #pragma unroll
            for (int nj = 0; nj < 4; nj++) {
                int row = wn + (nj << 4) + ((g4 >> 1) << 3) + r8;
                uint32_t addr = Bs_b
                    + (uint32_t)(row * KPW + s8) * 4 + ((g4 & 1) << 4);
                ldmatrix_x4(bf[2 * nj][0], bf[2 * nj][1],
                            bf[2 * nj + 1][0], bf[2 * nj + 1][1], addr);
            }

            #pragma unroll
            for (int mi = 0; mi < 4; mi++)
                #pragma unroll
                for (int ni = 0; ni < 8; ni++)
                    mma_f16(acc[mi][ni], af[mi], bf[ni]);
        }
    }

    // epilogue: bias add in fp32, then fp32 or fp16 store
    #pragma unroll
    for (int mi = 0; mi < 4; mi++) {
        int m = bm + wm + (mi << 4) + g;
        #pragma unroll
        for (int ni = 0; ni < 8; ni++) {
            int n = bn + wn + (ni << 3) + (q << 1);
            float2 bb = *(const float2*)&bias[n];
            float v00 = acc[mi][ni][0] + bb.x;
            float v01 = acc[mi][ni][1] + bb.y;
            float v10 = acc[mi][ni][2] + bb.x;
            float v11 = acc[mi][ni][3] + bb.y;
            if (Ch) {
                *(__half2*)&Ch[(size_t)m * N + n]       = __floats2half2_rn(v00, v01);
                *(__half2*)&Ch[(size_t)(m + 8) * N + n] = __floats2half2_rn(v10, v11);
            } else {
                *(float2*)&Cf[(size_t)m * N + n]       = make_float2(v00, v01);
                *(float2*)&Cf[(size_t)(m + 8) * N + n] = make_float2(v10, v11);
            }
        }
    }
}

// ---------------------------------------------------------------------------
// Prepass kernels (unchanged)
// ---------------------------------------------------------------------------
__global__ void cvt_f16_kernel(const float4* __restrict__ src,
                               __half2* __restrict__ dst, int n4)
{
    int i = blockIdx.x * blockDim.x + threadIdx.x;
    if (i < n4) {
        float4 v = src[i];
        dst[i * 2]     = __floats2half2_rn(v.x, v.y);
        dst[i * 2 + 1] = __floats2half2_rn(v.z, v.w);
    }
}

__global__ void transpose_f16_kernel(const float* __restrict__ src,
                                     __half* __restrict__ dst, int K, int N)
{
    __shared__ __half t[32][33];
    const int n0 = blockIdx.x * 32, k0 = blockIdx.y * 32;
    const int tx = threadIdx.x, ty = threadIdx.y;
    #pragma unroll
    for (int i = ty; i < 32; i += 8)
        t[i][tx] = __float2half_rn(src[(size_t)(k0 + i) * N + n0 + tx]);
    __syncthreads();
    #pragma unroll
    for (int i = ty; i < 32; i += 8)
        dst[(size_t)(n0 + i) * K + k0 + tx] = t[tx][i];
}

// ---------------------------------------------------------------------------
// Flash attention, fp16 mma.sync m16n8k16, causal. (round-13 proven)
// 64-row q-tile, 4 warps. smem tiles [64][36] words each.
// ---------------------------------------------------------------------------
#define AS 36
#define ATTN_SMEM_BYTES (4 * 64 * AS * 4)

__global__ __launch_bounds__(128) void attn_mma_kernel()
{
    extern __shared__ uint32_t smu[];
    uint32_t* Qs = smu;                 // [64][36] half2-words
    uint32_t* Ks = Qs + 64 * AS;
    uint32_t* Vs = Ks + 64 * AS;
    uint32_t* Ps = Vs + 64 * AS;
    const uint32_t vb = smem_u32(Vs);

    const int tid  = threadIdx.x;
    const int wid  = tid >> 5;
    const int lane = tid & 31;
    const int g = lane >> 2;
    const int q = lane & 3;
    const int l8 = lane & 7;
    const int lt = lane >> 3;

    const int qt = blockIdx.x;
    const int bh = blockIdx.y;
    const int b  = bh >> 4;
    const int h  = bh & (NHEAD - 1);

    const int q0 = qt * 64;
    const int qr = wid << 4;
    const float NEG = -1e30f;

    // stage Q: fp16 copy (uint2 = 4 halves)
    for (int i = tid; i < 1024; i += 128) {
        int row = i >> 4, c4 = (i & 15) << 2;
        uint2 v = *(const uint2*)(g_qkv_h
            + (size_t)(b * S_LEN + q0 + row) * (3 * DMODEL) + h * HD + c4);
        *(uint2*)&Qs[row * AS + (c4 >> 1)] = v;
    }

    float O[8][4];
    #pragma unroll
    for (int ni = 0; ni < 8; ni++)
        #pragma unroll
        for (int r = 0; r < 4; r++) O[ni][r] = 0.0f;
    float mrow0 = NEG, mrow1 = NEG, lrow0 = 0.0f, lrow1 = 0.0f;

    for (int kt = 0; kt <= qt; kt++) {
        const int k0 = kt * 64;
        __syncthreads();
        // stage K & V: fp16 copies
        for (int i = tid; i < 1024; i += 128) {
            int row = i >> 4, c4 = (i & 15) << 2;
            const __half* base = g_qkv_h
                + (size_t)(b * S_LEN + k0 + row) * (3 * DMODEL)
                + DMODEL + h * HD + c4;
            uint2 kv = *(const uint2*)base;
            uint2 vv = *(const uint2*)(base + DMODEL);
            *(uint2*)&Ks[row * AS + (c4 >> 1)] = kv;
            *(uint2*)&Vs[row * AS + (c4 >> 1)] = vv;
        }
        __syncthreads();

        // S = Q @ K^T
        float s[8][4];
        #pragma unroll
        for (int ni = 0; ni < 8; ni++)
            #pragma unroll
            for (int r = 0; r < 4; r++) s[ni][r] = 0.0f;

        #pragma unroll
        for (int ks = 0; ks < 4; ks++) {
            const int s8 = ks << 3;
            uint32_t a[4];
            const uint32_t* ar = Qs + (qr + g) * AS + s8 + q;
            a[0] = ar[0];
            a[1] = ar[8 * AS];
            a[2] = ar[4];
            a[3] = ar[8 * AS + 4];
            #pragma unroll
            for (int ni = 0; ni < 8; ni++) {
                const uint32_t* br = Ks + (ni * 8 + g) * AS + s8 + q;
                uint32_t bb[2] = { br[0], br[4] };
                mma_f16(s[ni], a, bb);
            }
        }

        // scale + causal mask (diagonal tile only)
        #pragma unroll
        for (int ni = 0; ni < 8; ni++)
            #pragma unroll
            for (int r = 0; r < 4; r++) s[ni][r] *= 0.125f;
        if (kt == qt) {
            int r0 = qr + g, r1 = qr + g + 8;
            #pragma unroll
            for (int ni = 0; ni < 8; ni++) {
                int c = ni * 8 + (q << 1);
                if (c > r0)     s[ni][0] = NEG;
                if (c + 1 > r0) s[ni][1] = NEG;
                if (c > r1)     s[ni][2] = NEG;
                if (c + 1 > r1) s[ni][3] = NEG;
            }
        }

        // online softmax
        float mx0 = NEG, mx1 = NEG;
        #pragma unroll
        for (int ni = 0; ni < 8; ni++) {
            mx0 = fmaxf(mx0, fmaxf(s[ni][0], s[ni][1]));
            mx1 = fmaxf(mx1, fmaxf(s[ni][2], s[ni][3]));
        }
        mx0 = fmaxf(mx0, __shfl_xor_sync(0xffffffffu, mx0, 1));
        mx0 = fmaxf(mx0, __shfl_xor_sync(0xffffffffu, mx0, 2));
        mx1 = fmaxf(mx1, __shfl_xor_sync(0xffffffffu, mx1, 1));
        mx1 = fmaxf(mx1, __shfl_xor_sync(0xffffffffu, mx1, 2));

        float mn0 = fmaxf(mrow0, mx0), mn1 = fmaxf(mrow1, mx1);
        float corr0 = __expf(mrow0 - mn0), corr1 = __expf(mrow1 - mn1);
        float sum0 = 0.0f, sum1 = 0.0f;
        #pragma unroll
        for (int ni = 0; ni < 8; ni++) {
            s[ni][0] = __expf(s[ni][0] - mn0);
            s[ni][1] = __expf(s[ni][1] - mn0);
            s[ni][2] = __expf(s[ni][2] - mn1);
            s[ni][3] = __expf(s[ni][3] - mn1);
            sum0 += s[ni][0] + s[ni][1];
            sum1 += s[ni][2] + s[ni][3];
        }
        sum0 += __shfl_xor_sync(0xffffffffu, sum0, 1);
        sum0 += __shfl_xor_sync(0xffffffffu, sum0, 2);
        sum1 += __shfl_xor_sync(0xffffffffu, sum1, 1);
        sum1 += __shfl_xor_sync(0xffffffffu, sum1, 2);
        lrow0 = lrow0 * corr0 + sum0;
        lrow1 = lrow1 * corr1 + sum1;
        mrow0 = mn0; mrow1 = mn1;
        #pragma unroll
        for (int ni = 0; ni < 8; ni++) {
            O[ni][0] *= corr0; O[ni][1] *= corr0;
            O[ni][2] *= corr1; O[ni][3] *= corr1;
        }

        // P -> smem fp16 (warp-private stripe)
        #pragma unroll
        for (int ni = 0; ni < 8; ni++) {
            Ps[(qr + g) * AS + ni * 4 + q] =
                h2u(__floats2half2_rn(s[ni][0], s[ni][1]));
            Ps[(qr + g + 8) * AS + ni * 4 + q] =
                h2u(__floats2half2_rn(s[ni][2], s[ni][3]));
        }
        __syncwarp();

        // O += P @ V : A-frag from Ps, B-frag from Vs via ldmatrix.trans
        #pragma unroll
        for (int ks = 0; ks < 4; ks++) {
            const int s8 = ks << 3;
            uint32_t a[4];
            const uint32_t* ar = Ps + (qr + g) * AS + s8 + q;
            a[0] = ar[0];
            a[1] = ar[8 * AS];
            a[2] = ar[4];
            a[3] = ar[8 * AS + 4];

            uint32_t vb0[8], vb1[8];
            #pragma unroll
            for (int m = 0; m < 4; m++) {
                uint32_t addr = vb + (uint32_t)(
                    (((ks << 4) + ((lt & 1) << 3) + l8) * AS
                     + ((m << 1) + (lt >> 1)) * 4) * 4);
                ldmatrix_x4_trans(vb0[2 * m], vb1[2 * m],
                                  vb0[2 * m + 1], vb1[2 * m + 1], addr);
            }
            #pragma unroll
            for (int ni = 0; ni < 8; ni++) {
                uint32_t bb[2] = { vb0[ni], vb1[ni] };
                mma_f16(O[ni], a, bb);
            }
        }
    }

    // normalize + store fp16 (proj GEMM consumes directly)
    float inv0 = 1.0f / lrow0, inv1 = 1.0f / lrow1;
    int r0 = q0 + qr + g, r1 = r0 + 8;
    __half* d0 = g_attn_h + (size_t)(b * S_LEN + r0) * DMODEL + h * HD;
    __half* d1 = g_attn_h + (size_t)(b * S_LEN + r1) * DMODEL + h * HD;
    #pragma unroll
    for (int ni = 0; ni < 8; ni++) {
        int c = ni * 8 + (q << 1);
        *(__half2*)&d0[c] = __floats2half2_rn(O[ni][0] * inv0, O[ni][1] * inv0);
        *(__half2*)&d1[c] = __floats2half2_rn(O[ni][2] * inv1, O[ni][3] * inv1);
    }
}

// ---------------------------------------------------------------------------
// kernel_launch: x, w_qkv, b_qkv, w_proj, b_proj
// ---------------------------------------------------------------------------
extern "C" void kernel_launch(void* const* d_in, const int* in_sizes, int n_in,
                              void* d_out, int out_size)
{
    const float* x      = (const float*)d_in[0];
    const float* w_qkv  = (const float*)d_in[1];
    const float* b_qkv  = (const float*)d_in[2];
    const float* w_proj = (const float*)d_in[3];
    const float* b_proj = (const float*)d_in[4];
    float* out = (float*)d_out;

    void *x_h, *wqkv_h, *wproj_h, *qkv_h, *attn_h;
    cudaGetSymbolAddress(&x_h, g_x_h);
    cudaGetSymbolAddress(&wqkv_h, g_wqkv_h);
    cudaGetSymbolAddress(&wproj_h, g_wproj_h);
    cudaGetSymbolAddress(&qkv_h, g_qkv_h);
    cudaGetSymbolAddress(&attn_h, g_attn_h);

    cudaFuncSetAttribute(f16_gemm_kernel,
                         cudaFuncAttributeMaxDynamicSharedMemorySize,
                         GEMM_SMEM_BYTES);
    cudaFuncSetAttribute(attn_mma_kernel,
                         cudaFuncAttributeMaxDynamicSharedMemorySize,
                         ATTN_SMEM_BYTES);

    // 0) prepass: x -> fp16; weights transpose-convert to [N][K] fp16
    {
        int n4x = MTOK * DMODEL / 4;
        cvt_f16_kernel<<<(n4x + 255) / 256, 256>>>(
            (const float4*)x, (__half2*)x_h, n4x);
        dim3 tblk(32, 8);
        dim3 tg1(3 * DMODEL / 32, DMODEL / 32);
        transpose_f16_kernel<<<tg1, tblk>>>(w_qkv, (__half*)wqkv_h,
                                            DMODEL, 3 * DMODEL);
        dim3 tg2(DMODEL / 32, DMODEL / 32);
        transpose_f16_kernel<<<tg2, tblk>>>(w_proj, (__half*)wproj_h,
                                            DMODEL, DMODEL);
    }

    // 1) QKV projection (fp16 MMA, fp16 output)
    {
        dim3 grid(3 * DMODEL / GBN, MTOK / GBM);
        f16_gemm_kernel<<<grid, 256, GEMM_SMEM_BYTES>>>(
            (const __half*)x_h, (const __half*)wqkv_h, b_qkv,
            nullptr, (__half*)qkv_h, MTOK, 3 * DMODEL, DMODEL);
    }

    // 2) causal flash attention (fp16 MMA, fp16 staging)
    {
        dim3 grid(S_LEN / 64, BATCH * NHEAD);
        attn_mma_kernel<<<grid, 128, ATTN_SMEM_BYTES>>>();
    }

    // 3) output projection (fp16 MMA, fp32 output)
    {
        dim3 grid(DMODEL / GBN, MTOK / GBM);
        f16_gemm_kernel<<<grid, 256, GEMM_SMEM_BYTES>>>(
            (const __half*)attn_h, (const __half*)wproj_h, b_proj,
            out, nullptr, MTOK, DMODEL, DMODEL);
    }
}

// round 15
// speedup vs baseline: 1.8652x; 1.0316x over previous
#include <cuda_runtime.h>
#include <cuda_fp16.h>
#include <math.h>
#include <stdint.h>

// Problem shape (fixed by the dataset)
#define BATCH   4
#define S_LEN   2048
#define DMODEL  1024
#define NHEAD   16
#define HD      64
#define MTOK    (BATCH * S_LEN)        // 8192 token rows

// ---------------------------------------------------------------------------
// Scratch (device globals: allocation-free)
// ---------------------------------------------------------------------------
__device__ __align__(16) __half g_x_h[(size_t)MTOK * DMODEL];          // x fp16
__device__ __align__(16) __half g_wqkv_h[(size_t)3 * DMODEL * DMODEL]; // w_qkv^T [N][K]
__device__ __align__(16) __half g_wproj_h[(size_t)DMODEL * DMODEL];    // w_proj^T [N][K]
__device__ __align__(16) __half g_qkv_h[(size_t)MTOK * 3 * DMODEL];    // fp16 qkv
__device__ __align__(16) __half g_attn_h[(size_t)MTOK * DMODEL];       // attn out fp16

// bit-reinterpret __half2 -> uint32
__device__ __forceinline__ uint32_t h2u(__half2 h) {
    union { __half2 h; uint32_t u; } c;
    c.h = h;
    return c.u;
}

__device__ __forceinline__ void mma_f16(float* c, const uint32_t* a,
                                        const uint32_t* b) {
    asm volatile(
        "mma.sync.aligned.m16n8k16.row.col.f32.f16.f16.f32 "
        "{%0,%1,%2,%3}, {%4,%5,%6,%7}, {%8,%9}, {%0,%1,%2,%3};"
        : "+f"(c[0]), "+f"(c[1]), "+f"(c[2]), "+f"(c[3])
        : "r"(a[0]), "r"(a[1]), "r"(a[2]), "r"(a[3]), "r"(b[0]), "r"(b[1]));
}

__device__ __forceinline__ void ldmatrix_x4(
    uint32_t& r0, uint32_t& r1, uint32_t& r2, uint32_t& r3, uint32_t addr) {
    asm volatile(
        "ldmatrix.sync.aligned.m8n8.x4.shared.b16 {%0,%1,%2,%3}, [%4];"
        : "=r"(r0), "=r"(r1), "=r"(r2), "=r"(r3) : "r"(addr));
}

__device__ __forceinline__ void ldmatrix_x4_trans(
    uint32_t& r0, uint32_t& r1, uint32_t& r2, uint32_t& r3, uint32_t addr) {
    asm volatile(
        "ldmatrix.sync.aligned.m8n8.x4.trans.shared.b16 {%0,%1,%2,%3}, [%4];"
        : "=r"(r0), "=r"(r1), "=r"(r2), "=r"(r3) : "r"(addr));
}

__device__ __forceinline__ uint32_t smem_u32(const void* p) {
    uint32_t a;
    asm("{ .reg .u64 t; cvta.to.shared.u64 t, %1; cvt.u32.u64 %0, t; }"
        : "=r"(a) : "l"(p));
    return a;
}
__device__ __forceinline__ void cp_async16(uint32_t dst, const void* src) {
    asm volatile("cp.async.cg.shared.global [%0], [%1], 16;"
                 :: "r"(dst), "l"(src));
}
#define CP_COMMIT()  asm volatile("cp.async.commit_group;" ::: "memory")
#define CP_WAIT1()   asm volatile("cp.async.wait_group 1;" ::: "memory")

// ---------------------------------------------------------------------------
// fp16 tensor-core GEMM: C[M,N] = A[M,K](f16) @ Bt[N,K](f16)^T + bias[N]
// Block 128x128, BK=32, 256 threads, 8 warps (2m x 4n), warp tile 64x32.
// 3-stage cp.async pipeline, 2 CTAs/SM (launch_bounds caps regs at 128).
// Fragment loads via ldmatrix.x4; row stride 20 words (conflict-free).
// Output: fp32 to Cf (if Ch == nullptr) or fp16 to Ch.
// ---------------------------------------------------------------------------
#define GBM 128
#define GBN 128
#define GBK 32
#define KPW 20
#define A_TW (128 * KPW)             // 2560 words
#define B_TW (128 * KPW)             // 2560 words
#define STG_W (A_TW + B_TW)          // 5120 words
#define GEMM_SMEM_BYTES (3 * STG_W * 4)   // 61440 B

__global__ __launch_bounds__(256, 2) void f16_gemm_kernel(
    const __half* __restrict__ A, const __half* __restrict__ Bt,
    const float* __restrict__ bias, float* __restrict__ Cf,
    __half* __restrict__ Ch, int M, int N, int K)
{
    extern __shared__ uint32_t smw[];
    const uint32_t smb = smem_u32(smw);

    const int tid  = threadIdx.x;
    const int wid  = tid >> 5;
    const int lane = tid & 31;
    const int g = lane >> 2;
    const int q = lane & 3;
    const int r8 = lane & 7;          // row within ldmatrix 8-group
    const int g4 = lane >> 3;         // ldmatrix address group 0..3

    const int wm = (wid & 1) << 6;    // 0 or 64
    const int wn = (wid >> 1) << 5;   // 0,32,64,96

    const int bm = blockIdx.y * GBM;
    const int bn = blockIdx.x * GBN;
    const int NT = K / GBK;

    // cp.async: A/B each 128 rows x 32 fp16 (64B = 4 cp16/row); 2 ops each
    const int c_row = tid >> 1;           // 0..127
    const int c_h   = (tid & 1) << 4;     // fp16 offset 0 or 16
    const int c_w   = (tid & 1) << 3;     // word offset 0 or 8

    auto issue = [&](int s, int kt) {
        uint32_t sb = smb + (uint32_t)(s * STG_W) * 4;
        const __half* Ar = A + (size_t)(bm + c_row) * K + kt * GBK + c_h;
        uint32_t ad = sb + (uint32_t)(c_row * KPW + c_w) * 4;
        cp_async16(ad, Ar);
        cp_async16(ad + 16, Ar + 8);
        const __half* Br = Bt + (size_t)(bn + c_row) * K + kt * GBK + c_h;
        uint32_t bd = sb + (uint32_t)(A_TW + c_row * KPW + c_w) * 4;
        cp_async16(bd, Br);
        cp_async16(bd + 16, Br + 8);
    };

    float acc[4][4][4];
    #pragma unroll
    for (int mi = 0; mi < 4; mi++)
        #pragma unroll
        for (int ni = 0; ni < 4; ni++)
            #pragma unroll
            for (int r = 0; r < 4; r++) acc[mi][ni][r] = 0.0f;

    issue(0, 0); CP_COMMIT();
    issue(1, 1); CP_COMMIT();

    for (int kt = 0; kt < NT; kt++) {
        CP_WAIT1();
        __syncthreads();
        if (kt + 2 < NT) issue((kt + 2) % 3, kt + 2);
        CP_COMMIT();

        const uint32_t As_b = smb + (uint32_t)((kt % 3) * STG_W) * 4;
        const uint32_t Bs_b = As_b + (uint32_t)A_TW * 4;

        #pragma unroll
        for (int s16 = 0; s16 < 2; s16++) {
            const int s8 = s16 << 3;                 // k word offset
            uint32_t af[4][4], bf[4][2];

            // A fragments: per mi one ldmatrix.x4
            #pragma unroll
            for (int mi = 0; mi < 4; mi++) {
                int row = wm + (mi << 4) + ((g4 & 1) << 3) + r8;
                uint32_t addr = As_b
                    + (uint32_t)(row * KPW + s8) * 4 + ((g4 >> 1) << 4);
                ldmatrix_x4(af[mi][0], af[mi][1], af[mi][2], af[mi][3], addr);
            }

            // B fragments: 2 ldmatrix.x4 cover n-pairs (0,1) and (2,3)
            #pragma unroll
            for (int nj = 0; nj < 2; nj++) {
                int row = wn + (nj << 4) + ((g4 >> 1) << 3) + r8;
                uint32_t addr = Bs_b
                    + (uint32_t)(row * KPW + s8) * 4 + ((g4 & 1) << 4);
                ldmatrix_x4(bf[2 * nj][0], bf[2 * nj][1],
                            bf[2 * nj + 1][0], bf[2 * nj + 1][1], addr);
            }

            #pragma unroll
            for (int mi = 0; mi < 4; mi++)
                #pragma unroll
                for (int ni = 0; ni < 4; ni++)
                    mma_f16(acc[mi][ni], af[mi], bf[ni]);
        }
    }

    // epilogue: bias add in fp32, then fp32 or fp16 store
    #pragma unroll
    for (int mi = 0; mi < 4; mi++) {
        int m = bm + wm + (mi << 4) + g;
        #pragma unroll
        for (int ni = 0; ni < 4; ni++) {
            int n = bn + wn + (ni << 3) + (q << 1);
            float2 bb = *(const float2*)&bias[n];
            float v00 = acc[mi][ni][0] + bb.x;
            float v01 = acc[mi][ni][1] + bb.y;
            float v10 = acc[mi][ni][2] + bb.x;
            float v11 = acc[mi][ni][3] + bb.y;
            if (Ch) {
                *(__half2*)&Ch[(size_t)m * N + n]       = __floats2half2_rn(v00, v01);
                *(__half2*)&Ch[(size_t)(m + 8) * N + n] = __floats2half2_rn(v10, v11);
            } else {
                *(float2*)&Cf[(size_t)m * N + n]       = make_float2(v00, v01);
                *(float2*)&Cf[(size_t)(m + 8) * N + n] = make_float2(v10, v11);
            }
        }
    }
}

// ---------------------------------------------------------------------------
// Prepass kernels (unchanged)
// ---------------------------------------------------------------------------
__global__ void cvt_f16_kernel(const float4* __restrict__ src,
                               __half2* __restrict__ dst, int n4)
{
    int i = blockIdx.x * blockDim.x + threadIdx.x;
    if (i < n4) {
        float4 v = src[i];
        dst[i * 2]     = __floats2half2_rn(v.x, v.y);
        dst[i * 2 + 1] = __floats2half2_rn(v.z, v.w);
    }
}

__global__ void transpose_f16_kernel(const float* __restrict__ src,
                                     __half* __restrict__ dst, int K, int N)
{
    __shared__ __half t[32][33];
    const int n0 = blockIdx.x * 32, k0 = blockIdx.y * 32;
    const int tx = threadIdx.x, ty = threadIdx.y;
    #pragma unroll
    for (int i = ty; i < 32; i += 8)
        t[i][tx] = __float2half_rn(src[(size_t)(k0 + i) * N + n0 + tx]);
    __syncthreads();
    #pragma unroll
    for (int i = ty; i < 32; i += 8)
        dst[(size_t)(n0 + i) * K + k0 + tx] = t[tx][i];
}

// ---------------------------------------------------------------------------
// Flash attention, fp16 mma.sync m16n8k16, causal. (round-13 proven)
// 64-row q-tile, 4 warps. smem tiles [64][36] words each.
// ---------------------------------------------------------------------------
#define AS 36
#define ATTN_SMEM_BYTES (4 * 64 * AS * 4)

__global__ __launch_bounds__(128) void attn_mma_kernel()
{
    extern __shared__ uint32_t smu[];
    uint32_t* Qs = smu;                 // [64][36] half2-words
    uint32_t* Ks = Qs + 64 * AS;
    uint32_t* Vs = Ks + 64 * AS;
    uint32_t* Ps = Vs + 64 * AS;
    const uint32_t vb = smem_u32(Vs);

    const int tid  = threadIdx.x;
    const int wid  = tid >> 5;
    const int lane = tid & 31;
    const int g = lane >> 2;
    const int q = lane & 3;
    const int l8 = lane & 7;
    const int lt = lane >> 3;

    const int qt = blockIdx.x;
    const int bh = blockIdx.y;
    const int b  = bh >> 4;
    const int h  = bh & (NHEAD - 1);

    const int q0 = qt * 64;
    const int qr = wid << 4;
    const float NEG = -1e30f;

    // stage Q: fp16 copy (uint2 = 4 halves)
    for (int i = tid; i < 1024; i += 128) {
        int row = i >> 4, c4 = (i & 15) << 2;
        uint2 v = *(const uint2*)(g_qkv_h
            + (size_t)(b * S_LEN + q0 + row) * (3 * DMODEL) + h * HD + c4);
        *(uint2*)&Qs[row * AS + (c4 >> 1)] = v;
    }

    float O[8][4];
    #pragma unroll
    for (int ni = 0; ni < 8; ni++)
        #pragma unroll
        for (int r = 0; r < 4; r++) O[ni][r] = 0.0f;
    float mrow0 = NEG, mrow1 = NEG, lrow0 = 0.0f, lrow1 = 0.0f;

    for (int kt = 0; kt <= qt; kt++) {
        const int k0 = kt * 64;
        __syncthreads();
        // stage K & V: fp16 copies
        for (int i = tid; i < 1024; i += 128) {
            int row = i >> 4, c4 = (i & 15) << 2;
            const __half* base = g_qkv_h
                + (size_t)(b * S_LEN + k0 + row) * (3 * DMODEL)
                + DMODEL + h * HD + c4;
            uint2 kv = *(const uint2*)base;
            uint2 vv = *(const uint2*)(base + DMODEL);
            *(uint2*)&Ks[row * AS + (c4 >> 1)] = kv;
            *(uint2*)&Vs[row * AS + (c4 >> 1)] = vv;
        }
        __syncthreads();

        // S = Q @ K^T
        float s[8][4];
        #pragma unroll
        for (int ni = 0; ni < 8; ni++)
            #pragma unroll
            for (int r = 0; r < 4; r++) s[ni][r] = 0.0f;

        #pragma unroll
        for (int ks = 0; ks < 4; ks++) {
            const int s8 = ks << 3;
            uint32_t a[4];
            const uint32_t* ar = Qs + (qr + g) * AS + s8 + q;
            a[0] = ar[0];
            a[1] = ar[8 * AS];
            a[2] = ar[4];
            a[3] = ar[8 * AS + 4];
            #pragma unroll
            for (int ni = 0; ni < 8; ni++) {
                const uint32_t* br = Ks + (ni * 8 + g) * AS + s8 + q;
                uint32_t bb[2] = { br[0], br[4] };
                mma_f16(s[ni], a, bb);
            }
        }

        // scale + causal mask (diagonal tile only)
        #pragma unroll
        for (int ni = 0; ni < 8; ni++)
            #pragma unroll
            for (int r = 0; r < 4; r++) s[ni][r] *= 0.125f;
        if (kt == qt) {
            int r0 = qr + g, r1 = qr + g + 8;
            #pragma unroll
            for (int ni = 0; ni < 8; ni++) {
                int c = ni * 8 + (q << 1);
                if (c > r0)     s[ni][0] = NEG;
                if (c + 1 > r0) s[ni][1] = NEG;
                if (c > r1)     s[ni][2] = NEG;
                if (c + 1 > r1) s[ni][3] = NEG;
            }
        }

        // online softmax
        float mx0 = NEG, mx1 = NEG;
        #pragma unroll
        for (int ni = 0; ni < 8; ni++) {
            mx0 = fmaxf(mx0, fmaxf(s[ni][0], s[ni][1]));
            mx1 = fmaxf(mx1, fmaxf(s[ni][2], s[ni][3]));
        }
        mx0 = fmaxf(mx0, __shfl_xor_sync(0xffffffffu, mx0, 1));
        mx0 = fmaxf(mx0, __shfl_xor_sync(0xffffffffu, mx0, 2));
        mx1 = fmaxf(mx1, __shfl_xor_sync(0xffffffffu, mx1, 1));
        mx1 = fmaxf(mx1, __shfl_xor_sync(0xffffffffu, mx1, 2));

        float mn0 = fmaxf(mrow0, mx0), mn1 = fmaxf(mrow1, mx1);
        float corr0 = __expf(mrow0 - mn0), corr1 = __expf(mrow1 - mn1);
        float sum0 = 0.0f, sum1 = 0.0f;
        #pragma unroll
        for (int ni = 0; ni < 8; ni++) {
            s[ni][0] = __expf(s[ni][0] - mn0);
            s[ni][1] = __expf(s[ni][1] - mn0);
            s[ni][2] = __expf(s[ni][2] - mn1);
            s[ni][3] = __expf(s[ni][3] - mn1);
            sum0 += s[ni][0] + s[ni][1];
            sum1 += s[ni][2] + s[ni][3];
        }
        sum0 += __shfl_xor_sync(0xffffffffu, sum0, 1);
        sum0 += __shfl_xor_sync(0xffffffffu, sum0, 2);
        sum1 += __shfl_xor_sync(0xffffffffu, sum1, 1);
        sum1 += __shfl_xor_sync(0xffffffffu, sum1, 2);
        lrow0 = lrow0 * corr0 + sum0;
        lrow1 = lrow1 * corr1 + sum1;
        mrow0 = mn0; mrow1 = mn1;
        #pragma unroll
        for (int ni = 0; ni < 8; ni++) {
            O[ni][0] *= corr0; O[ni][1] *= corr0;
            O[ni][2] *= corr1; O[ni][3] *= corr1;
        }

        // P -> smem fp16 (warp-private stripe)
        #pragma unroll
        for (int ni = 0; ni < 8; ni++) {
            Ps[(qr + g) * AS + ni * 4 + q] =
                h2u(__floats2half2_rn(s[ni][0], s[ni][1]));
            Ps[(qr + g + 8) * AS + ni * 4 + q] =
                h2u(__floats2half2_rn(s[ni][2], s[ni][3]));
        }
        __syncwarp();

        // O += P @ V : A-frag from Ps, B-frag from Vs via ldmatrix.trans
        #pragma unroll
        for (int ks = 0; ks < 4; ks++) {
            const int s8 = ks << 3;
            uint32_t a[4];
            const uint32_t* ar = Ps + (qr + g) * AS + s8 + q;
            a[0] = ar[0];
            a[1] = ar[8 * AS];
            a[2] = ar[4];
            a[3] = ar[8 * AS + 4];

            uint32_t vb0[8], vb1[8];
            #pragma unroll
            for (int m = 0; m < 4; m++) {
                uint32_t addr = vb + (uint32_t)(
                    (((ks << 4) + ((lt & 1) << 3) + l8) * AS
                     + ((m << 1) + (lt >> 1)) * 4) * 4);
                ldmatrix_x4_trans(vb0[2 * m], vb1[2 * m],
                                  vb0[2 * m + 1], vb1[2 * m + 1], addr);
            }
            #pragma unroll
            for (int ni = 0; ni < 8; ni++) {
                uint32_t bb[2] = { vb0[ni], vb1[ni] };
                mma_f16(O[ni], a, bb);
            }
        }
    }

    // normalize + store fp16 (proj GEMM consumes directly)
    float inv0 = 1.0f / lrow0, inv1 = 1.0f / lrow1;
    int r0 = q0 + qr + g, r1 = r0 + 8;
    __half* d0 = g_attn_h + (size_t)(b * S_LEN + r0) * DMODEL + h * HD;
    __half* d1 = g_attn_h + (size_t)(b * S_LEN + r1) * DMODEL + h * HD;
    #pragma unroll
    for (int ni = 0; ni < 8; ni++) {
        int c = ni * 8 + (q << 1);
        *(__half2*)&d0[c] = __floats2half2_rn(O[ni][0] * inv0, O[ni][1] * inv0);
        *(__half2*)&d1[c] = __floats2half2_rn(O[ni][2] * inv1, O[ni][3] * inv1);
    }
}

// ---------------------------------------------------------------------------
// kernel_launch: x, w_qkv, b_qkv, w_proj, b_proj
// ---------------------------------------------------------------------------
extern "C" void kernel_launch(void* const* d_in, const int* in_sizes, int n_in,
                              void* d_out, int out_size)
{
    const float* x      = (const float*)d_in[0];
    const float* w_qkv  = (const float*)d_in[1];
    const float* b_qkv  = (const float*)d_in[2];
    const float* w_proj = (const float*)d_in[3];
    const float* b_proj = (const float*)d_in[4];
    float* out = (float*)d_out;

    void *x_h, *wqkv_h, *wproj_h, *qkv_h, *attn_h;
    cudaGetSymbolAddress(&x_h, g_x_h);
    cudaGetSymbolAddress(&wqkv_h, g_wqkv_h);
    cudaGetSymbolAddress(&wproj_h, g_wproj_h);
    cudaGetSymbolAddress(&qkv_h, g_qkv_h);
    cudaGetSymbolAddress(&attn_h, g_attn_h);

    cudaFuncSetAttribute(f16_gemm_kernel,
                         cudaFuncAttributeMaxDynamicSharedMemorySize,
                         GEMM_SMEM_BYTES);
    cudaFuncSetAttribute(attn_mma_kernel,
                         cudaFuncAttributeMaxDynamicSharedMemorySize,
                         ATTN_SMEM_BYTES);

    // 0) prepass: x -> fp16; weights transpose-convert to [N][K] fp16
    {
        int n4x = MTOK * DMODEL / 4;
        cvt_f16_kernel<<<(n4x + 255) / 256, 256>>>(
            (const float4*)x, (__half2*)x_h, n4x);
        dim3 tblk(32, 8);
        dim3 tg1(3 * DMODEL / 32, DMODEL / 32);
        transpose_f16_kernel<<<tg1, tblk>>>(w_qkv, (__half*)wqkv_h,
                                            DMODEL, 3 * DMODEL);
        dim3 tg2(DMODEL / 32, DMODEL / 32);
        transpose_f16_kernel<<<tg2, tblk>>>(w_proj, (__half*)wproj_h,
                                            DMODEL, DMODEL);
    }

    // 1) QKV projection (fp16 MMA, fp16 output)
    {
        dim3 grid(3 * DMODEL / GBN, MTOK / GBM);
        f16_gemm_kernel<<<grid, 256, GEMM_SMEM_BYTES>>>(
            (const __half*)x_h, (const __half*)wqkv_h, b_qkv,
            nullptr, (__half*)qkv_h, MTOK, 3 * DMODEL, DMODEL);
    }

    // 2) causal flash attention (fp16 MMA, fp16 staging)
    {
        dim3 grid(S_LEN / 64, BATCH * NHEAD);
        attn_mma_kernel<<<grid, 128, ATTN_SMEM_BYTES>>>();
    }

    // 3) output projection (fp16 MMA, fp32 output)
    {
        dim3 grid(DMODEL / GBN, MTOK / GBM);
        f16_gemm_kernel<<<grid, 256, GEMM_SMEM_BYTES>>>(
            (const __half*)attn_h, (const __half*)wproj_h, b_proj,
            out, nullptr, MTOK, DMODEL, DMODEL);
    }
}

// round 16
// speedup vs baseline: 1.9662x; 1.0542x over previous
#include <cuda_runtime.h>
#include <cuda_fp16.h>
#include <math.h>
#include <stdint.h>

// Problem shape (fixed by the dataset)
#define BATCH   4
#define S_LEN   2048
#define DMODEL  1024
#define NHEAD   16
#define HD      64
#define MTOK    (BATCH * S_LEN)        // 8192 token rows

// ---------------------------------------------------------------------------
// Scratch (device globals: allocation-free)
// ---------------------------------------------------------------------------
__device__ __align__(16) __half g_x_h[(size_t)MTOK * DMODEL];          // x fp16
__device__ __align__(16) __half g_wqkv_h[(size_t)3 * DMODEL * DMODEL]; // w_qkv^T [N][K]
__device__ __align__(16) __half g_wproj_h[(size_t)DMODEL * DMODEL];    // w_proj^T [N][K]
__device__ __align__(16) __half g_qkv_h[(size_t)MTOK * 3 * DMODEL];    // fp16 qkv
__device__ __align__(16) __half g_attn_h[(size_t)MTOK * DMODEL];       // attn out fp16

// bit-reinterpret __half2 -> uint32
__device__ __forceinline__ uint32_t h2u(__half2 h) {
    union { __half2 h; uint32_t u; } c;
    c.h = h;
    return c.u;
}

__device__ __forceinline__ void mma_f16(float* c, const uint32_t* a,
                                        const uint32_t* b) {
    asm volatile(
        "mma.sync.aligned.m16n8k16.row.col.f32.f16.f16.f32 "
        "{%0,%1,%2,%3}, {%4,%5,%6,%7}, {%8,%9}, {%0,%1,%2,%3};"
        : "+f"(c[0]), "+f"(c[1]), "+f"(c[2]), "+f"(c[3])
        : "r"(a[0]), "r"(a[1]), "r"(a[2]), "r"(a[3]), "r"(b[0]), "r"(b[1]));
}

__device__ __forceinline__ void ldmatrix_x4(
    uint32_t& r0, uint32_t& r1, uint32_t& r2, uint32_t& r3, uint32_t addr) {
    asm volatile(
        "ldmatrix.sync.aligned.m8n8.x4.shared.b16 {%0,%1,%2,%3}, [%4];"
        : "=r"(r0), "=r"(r1), "=r"(r2), "=r"(r3) : "r"(addr));
}

__device__ __forceinline__ void ldmatrix_x4_trans(
    uint32_t& r0, uint32_t& r1, uint32_t& r2, uint32_t& r3, uint32_t addr) {
    asm volatile(
        "ldmatrix.sync.aligned.m8n8.x4.trans.shared.b16 {%0,%1,%2,%3}, [%4];"
        : "=r"(r0), "=r"(r1), "=r"(r2), "=r"(r3) : "r"(addr));
}

__device__ __forceinline__ uint32_t smem_u32(const void* p) {
    uint32_t a;
    asm("{ .reg .u64 t; cvta.to.shared.u64 t, %1; cvt.u32.u64 %0, t; }"
        : "=r"(a) : "l"(p));
    return a;
}
__device__ __forceinline__ void cp_async16(uint32_t dst, const void* src) {
    asm volatile("cp.async.cg.shared.global [%0], [%1], 16;"
                 :: "r"(dst), "l"(src));
}
#define CP_COMMIT()  asm volatile("cp.async.commit_group;" ::: "memory")
#define CP_WAIT1()   asm volatile("cp.async.wait_group 1;" ::: "memory")
#define CP_WAIT0()   asm volatile("cp.async.wait_group 0;" ::: "memory")

// ---------------------------------------------------------------------------
// fp16 tensor-core GEMM (round-15 proven, unchanged).
// Block 128x128, BK=32, 256 threads, 8 warps (2m x 4n), warp tile 64x32.
// 3-stage cp.async pipeline, 2 CTAs/SM. ldmatrix fragments.
// ---------------------------------------------------------------------------
#define GBM 128
#define GBN 128
#define GBK 32
#define KPW 20
#define A_TW (128 * KPW)
#define B_TW (128 * KPW)
#define STG_W (A_TW + B_TW)
#define GEMM_SMEM_BYTES (3 * STG_W * 4)   // 61440 B

__global__ __launch_bounds__(256, 2) void f16_gemm_kernel(
    const __half* __restrict__ A, const __half* __restrict__ Bt,
    const float* __restrict__ bias, float* __restrict__ Cf,
    __half* __restrict__ Ch, int M, int N, int K)
{
    extern __shared__ uint32_t smw[];
    const uint32_t smb = smem_u32(smw);

    const int tid  = threadIdx.x;
    const int wid  = tid >> 5;
    const int lane = tid & 31;
    const int g = lane >> 2;
    const int q = lane & 3;
    const int r8 = lane & 7;
    const int g4 = lane >> 3;

    const int wm = (wid & 1) << 6;
    const int wn = (wid >> 1) << 5;

    const int bm = blockIdx.y * GBM;
    const int bn = blockIdx.x * GBN;
    const int NT = K / GBK;

    const int c_row = tid >> 1;
    const int c_h   = (tid & 1) << 4;
    const int c_w   = (tid & 1) << 3;

    auto issue = [&](int s, int kt) {
        uint32_t sb = smb + (uint32_t)(s * STG_W) * 4;
        const __half* Ar = A + (size_t)(bm + c_row) * K + kt * GBK + c_h;
        uint32_t ad = sb + (uint32_t)(c_row * KPW + c_w) * 4;
        cp_async16(ad, Ar);
        cp_async16(ad + 16, Ar + 8);
        const __half* Br = Bt + (size_t)(bn + c_row) * K + kt * GBK + c_h;
        uint32_t bd = sb + (uint32_t)(A_TW + c_row * KPW + c_w) * 4;
        cp_async16(bd, Br);
        cp_async16(bd + 16, Br + 8);
    };

    float acc[4][4][4];
    #pragma unroll
    for (int mi = 0; mi < 4; mi++)
        #pragma unroll
        for (int ni = 0; ni < 4; ni++)
            #pragma unroll
            for (int r = 0; r < 4; r++) acc[mi][ni][r] = 0.0f;

    issue(0, 0); CP_COMMIT();
    issue(1, 1); CP_COMMIT();

    for (int kt = 0; kt < NT; kt++) {
        CP_WAIT1();
        __syncthreads();
        if (kt + 2 < NT) issue((kt + 2) % 3, kt + 2);
        CP_COMMIT();

        const uint32_t As_b = smb + (uint32_t)((kt % 3) * STG_W) * 4;
        const uint32_t Bs_b = As_b + (uint32_t)A_TW * 4;

        #pragma unroll
        for (int s16 = 0; s16 < 2; s16++) {
            const int s8 = s16 << 3;
            uint32_t af[4][4], bf[4][2];

            #pragma unroll
            for (int mi = 0; mi < 4; mi++) {
                int row = wm + (mi << 4) + ((g4 & 1) << 3) + r8;
                uint32_t addr = As_b
                    + (uint32_t)(row * KPW + s8) * 4 + ((g4 >> 1) << 4);
                ldmatrix_x4(af[mi][0], af[mi][1], af[mi][2], af[mi][3], addr);
            }
            #pragma unroll
            for (int nj = 0; nj < 2; nj++) {
                int row = wn + (nj << 4) + ((g4 >> 1) << 3) + r8;
                uint32_t addr = Bs_b
                    + (uint32_t)(row * KPW + s8) * 4 + ((g4 & 1) << 4);
                ldmatrix_x4(bf[2 * nj][0], bf[2 * nj][1],
                            bf[2 * nj + 1][0], bf[2 * nj + 1][1], addr);
            }
            #pragma unroll
            for (int mi = 0; mi < 4; mi++)
                #pragma unroll
                for (int ni = 0; ni < 4; ni++)
                    mma_f16(acc[mi][ni], af[mi], bf[ni]);
        }
    }

    #pragma unroll
    for (int mi = 0; mi < 4; mi++) {
        int m = bm + wm + (mi << 4) + g;
        #pragma unroll
        for (int ni = 0; ni < 4; ni++) {
            int n = bn + wn + (ni << 3) + (q << 1);
            float2 bb = *(const float2*)&bias[n];
            float v00 = acc[mi][ni][0] + bb.x;
            float v01 = acc[mi][ni][1] + bb.y;
            float v10 = acc[mi][ni][2] + bb.x;
            float v11 = acc[mi][ni][3] + bb.y;
            if (Ch) {
                *(__half2*)&Ch[(size_t)m * N + n]       = __floats2half2_rn(v00, v01);
                *(__half2*)&Ch[(size_t)(m + 8) * N + n] = __floats2half2_rn(v10, v11);
            } else {
                *(float2*)&Cf[(size_t)m * N + n]       = make_float2(v00, v01);
                *(float2*)&Cf[(size_t)(m + 8) * N + n] = make_float2(v10, v11);
            }
        }
    }
}

// ---------------------------------------------------------------------------
// Prepass kernels (unchanged)
// ---------------------------------------------------------------------------
__global__ void cvt_f16_kernel(const float4* __restrict__ src,
                               __half2* __restrict__ dst, int n4)
{
    int i = blockIdx.x * blockDim.x + threadIdx.x;
    if (i < n4) {
        float4 v = src[i];
        dst[i * 2]     = __floats2half2_rn(v.x, v.y);
        dst[i * 2 + 1] = __floats2half2_rn(v.z, v.w);
    }
}

__global__ void transpose_f16_kernel(const float* __restrict__ src,
                                     __half* __restrict__ dst, int K, int N)
{
    __shared__ __half t[32][33];
    const int n0 = blockIdx.x * 32, k0 = blockIdx.y * 32;
    const int tx = threadIdx.x, ty = threadIdx.y;
    #pragma unroll
    for (int i = ty; i < 32; i += 8)
        t[i][tx] = __float2half_rn(src[(size_t)(k0 + i) * N + n0 + tx]);
    __syncthreads();
    #pragma unroll
    for (int i = ty; i < 32; i += 8)
        dst[(size_t)(n0 + i) * K + k0 + tx] = t[tx][i];
}

// ---------------------------------------------------------------------------
// Flash attention, fp16 mma.sync m16n8k16, causal.
// 64-row q-tile, 4 warps. cp.async DOUBLE-BUFFERED K/V staging.
// smem: Qs[64][36], Kb[2][64][36], Vb[2][64][36], Ps[64][36] = 55296 B.
// ---------------------------------------------------------------------------
#define AS 36
#define TILE_W (64 * AS)
#define ATTN_SMEM_BYTES (6 * TILE_W * 4)

__global__ __launch_bounds__(128) void attn_mma_kernel()
{
    extern __shared__ uint32_t smu[];
    uint32_t* Qs = smu;                 // [64][36]
    uint32_t* Kb = Qs + TILE_W;         // [2][64][36]
    uint32_t* Vb = Kb + 2 * TILE_W;     // [2][64][36]
    uint32_t* Ps = Vb + 2 * TILE_W;     // [64][36]
    const uint32_t kb_sm = smem_u32(Kb);
    const uint32_t vb_sm = smem_u32(Vb);

    const int tid  = threadIdx.x;
    const int wid  = tid >> 5;
    const int lane = tid & 31;
    const int g = lane >> 2;
    const int q = lane & 3;
    const int l8 = lane & 7;
    const int lt = lane >> 3;

    const int qt = blockIdx.x;
    const int bh = blockIdx.y;
    const int b  = bh >> 4;
    const int h  = bh & (NHEAD - 1);

    const int q0 = qt * 64;
    const int qr = wid << 4;
    const float NEG = -1e30f;

    // cp.async K/V tile stage: 64 rows x 64 halves each = 512 cp16 per tensor;
    // per thread 4 K + 4 V. row = idx>>3, ch = (idx&7)*8 halves (full row!)
    auto issue_kv = [&](int stage, int kt) {
        const int k0 = kt * 64;
        uint32_t kd = kb_sm + (uint32_t)(stage * TILE_W) * 4;
        uint32_t vd = vb_sm + (uint32_t)(stage * TILE_W) * 4;
        #pragma unroll
        for (int r = 0; r < 4; r++) {
            int idx = tid + (r << 7);          // 0..511
            int row = idx >> 3;                // 0..63
            int ch  = (idx & 7) << 3;          // half offset 0..56
            const __half* kg = g_qkv_h
                + (size_t)(b * S_LEN + k0 + row) * (3 * DMODEL)
                + DMODEL + h * HD + ch;
            uint32_t off = (uint32_t)(row * AS + (ch >> 1)) * 4;
            cp_async16(kd + off, kg);
            cp_async16(vd + off, kg + DMODEL);
        }
    };

    // stage Q (fp16 copy, once)
    for (int i = tid; i < 1024; i += 128) {
        int row = i >> 4, c4 = (i & 15) << 2;
        uint2 v = *(const uint2*)(g_qkv_h
            + (size_t)(b * S_LEN + q0 + row) * (3 * DMODEL) + h * HD + c4);
        *(uint2*)&Qs[row * AS + (c4 >> 1)] = v;
    }

    float O[8][4];
    #pragma unroll
    for (int ni = 0; ni < 8; ni++)
        #pragma unroll
        for (int r = 0; r < 4; r++) O[ni][r] = 0.0f;
    float mrow0 = NEG, mrow1 = NEG, lrow0 = 0.0f, lrow1 = 0.0f;

    issue_kv(0, 0); CP_COMMIT();

    for (int kt = 0; kt <= qt; kt++) {
        __syncthreads();   // all warps done reading buffer (kt+1)&1 (prev iter)
        if (kt < qt) { issue_kv((kt + 1) & 1, kt + 1); CP_COMMIT(); CP_WAIT1(); }
        else         { CP_WAIT0(); }
        __syncthreads();   // buffer kt&1 visible to all warps

        const uint32_t* Ks = Kb + (kt & 1) * TILE_W;
        const uint32_t  vsb = vb_sm + (uint32_t)((kt & 1) * TILE_W) * 4;

        // S = Q @ K^T
        float s[8][4];
        #pragma unroll
        for (int ni = 0; ni < 8; ni++)
            #pragma unroll
            for (int r = 0; r < 4; r++) s[ni][r] = 0.0f;

        #pragma unroll
        for (int ks = 0; ks < 4; ks++) {
            const int s8 = ks << 3;
            uint32_t a[4];
            const uint32_t* ar = Qs + (qr + g) * AS + s8 + q;
            a[0] = ar[0];
            a[1] = ar[8 * AS];
            a[2] = ar[4];
            a[3] = ar[8 * AS + 4];
            #pragma unroll
            for (int ni = 0; ni < 8; ni++) {
                const uint32_t* br = Ks + (ni * 8 + g) * AS + s8 + q;
                uint32_t bb[2] = { br[0], br[4] };
                mma_f16(s[ni], a, bb);
            }
        }

        // scale + causal mask (diagonal tile only)
        #pragma unroll
        for (int ni = 0; ni < 8; ni++)
            #pragma unroll
            for (int r = 0; r < 4; r++) s[ni][r] *= 0.125f;
        if (kt == qt) {
            int r0 = qr + g, r1 = qr + g + 8;
            #pragma unroll
            for (int ni = 0; ni < 8; ni++) {
                int c = ni * 8 + (q << 1);
                if (c > r0)     s[ni][0] = NEG;
                if (c + 1 > r0) s[ni][1] = NEG;
                if (c > r1)     s[ni][2] = NEG;
                if (c + 1 > r1) s[ni][3] = NEG;
            }
        }

        // online softmax
        float mx0 = NEG, mx1 = NEG;
        #pragma unroll
        for (int ni = 0; ni < 8; ni++) {
            mx0 = fmaxf(mx0, fmaxf(s[ni][0], s[ni][1]));
            mx1 = fmaxf(mx1, fmaxf(s[ni][2], s[ni][3]));
        }
        mx0 = fmaxf(mx0, __shfl_xor_sync(0xffffffffu, mx0, 1));
        mx0 = fmaxf(mx0, __shfl_xor_sync(0xffffffffu, mx0, 2));
        mx1 = fmaxf(mx1, __shfl_xor_sync(0xffffffffu, mx1, 1));
        mx1 = fmaxf(mx1, __shfl_xor_sync(0xffffffffu, mx1, 2));

        float mn0 = fmaxf(mrow0, mx0), mn1 = fmaxf(mrow1, mx1);
        float corr0 = __expf(mrow0 - mn0), corr1 = __expf(mrow1 - mn1);
        float sum0 = 0.0f, sum1 = 0.0f;
        #pragma unroll
        for (int ni = 0; ni < 8; ni++) {
            s[ni][0] = __expf(s[ni][0] - mn0);
            s[ni][1] = __expf(s[ni][1] - mn0);
            s[ni][2] = __expf(s[ni][2] - mn1);
            s[ni][3] = __expf(s[ni][3] - mn1);
            sum0 += s[ni][0] + s[ni][1];
            sum1 += s[ni][2] + s[ni][3];
        }
        sum0 += __shfl_xor_sync(0xffffffffu, sum0, 1);
        sum0 += __shfl_xor_sync(0xffffffffu, sum0, 2);
        sum1 += __shfl_xor_sync(0xffffffffu, sum1, 1);
        sum1 += __shfl_xor_sync(0xffffffffu, sum1, 2);
        lrow0 = lrow0 * corr0 + sum0;
        lrow1 = lrow1 * corr1 + sum1;
        mrow0 = mn0; mrow1 = mn1;
        #pragma unroll
        for (int ni = 0; ni < 8; ni++) {
            O[ni][0] *= corr0; O[ni][1] *= corr0;
            O[ni][2] *= corr1; O[ni][3] *= corr1;
        }

        // P -> smem fp16 (warp-private stripe)
        #pragma unroll
        for (int ni = 0; ni < 8; ni++) {
            Ps[(qr + g) * AS + ni * 4 + q] =
                h2u(__floats2half2_rn(s[ni][0], s[ni][1]));
            Ps[(qr + g + 8) * AS + ni * 4 + q] =
                h2u(__floats2half2_rn(s[ni][2], s[ni][3]));
        }
        __syncwarp();

        // O += P @ V : A-frag from Ps, B-frag from V via ldmatrix.trans
        #pragma unroll
        for (int ks = 0; ks < 4; ks++) {
            const int s8 = ks << 3;
            uint32_t a[4];
            const uint32_t* ar = Ps + (qr + g) * AS + s8 + q;
            a[0] = ar[0];
            a[1] = ar[8 * AS];
            a[2] = ar[4];
            a[3] = ar[8 * AS + 4];

            uint32_t vb0[8], vb1[8];
            #pragma unroll
            for (int m = 0; m < 4; m++) {
                uint32_t addr = vsb + (uint32_t)(
                    (((ks << 4) + ((lt & 1) << 3) + l8) * AS
                     + ((m << 1) + (lt >> 1)) * 4) * 4);
                ldmatrix_x4_trans(vb0[2 * m], vb1[2 * m],
                                  vb0[2 * m + 1], vb1[2 * m + 1], addr);
            }
            #pragma unroll
            for (int ni = 0; ni < 8; ni++) {
                uint32_t bb[2] = { vb0[ni], vb1[ni] };
                mma_f16(O[ni], a, bb);
            }
        }
    }

    // normalize + store fp16
    float inv0 = 1.0f / lrow0, inv1 = 1.0f / lrow1;
    int r0 = q0 + qr + g, r1 = r0 + 8;
    __half* d0 = g_attn_h + (size_t)(b * S_LEN + r0) * DMODEL + h * HD;
    __half* d1 = g_attn_h + (size_t)(b * S_LEN + r1) * DMODEL + h * HD;
    #pragma unroll
    for (int ni = 0; ni < 8; ni++) {
        int c = ni * 8 + (q << 1);
        *(__half2*)&d0[c] = __floats2half2_rn(O[ni][0] * inv0, O[ni][1] * inv0);
        *(__half2*)&d1[c] = __floats2half2_rn(O[ni][2] * inv1, O[ni][3] * inv1);
    }
}

// ---------------------------------------------------------------------------
// kernel_launch: x, w_qkv, b_qkv, w_proj, b_proj
// ---------------------------------------------------------------------------
extern "C" void kernel_launch(void* const* d_in, const int* in_sizes, int n_in,
                              void* d_out, int out_size)
{
    const float* x      = (const float*)d_in[0];
    const float* w_qkv  = (const float*)d_in[1];
    const float* b_qkv  = (const float*)d_in[2];
    const float* w_proj = (const float*)d_in[3];
    const float* b_proj = (const float*)d_in[4];
    float* out = (float*)d_out;

    void *x_h, *wqkv_h, *wproj_h, *qkv_h, *attn_h;
    cudaGetSymbolAddress(&x_h, g_x_h);
    cudaGetSymbolAddress(&wqkv_h, g_wqkv_h);
    cudaGetSymbolAddress(&wproj_h, g_wproj_h);
    cudaGetSymbolAddress(&qkv_h, g_qkv_h);
    cudaGetSymbolAddress(&attn_h, g_attn_h);

    cudaFuncSetAttribute(f16_gemm_kernel,
                         cudaFuncAttributeMaxDynamicSharedMemorySize,
                         GEMM_SMEM_BYTES);
    cudaFuncSetAttribute(attn_mma_kernel,
                         cudaFuncAttributeMaxDynamicSharedMemorySize,
                         ATTN_SMEM_BYTES);

    // 0) prepass: x -> fp16; weights transpose-convert to [N][K] fp16
    {
        int n4x = MTOK * DMODEL / 4;
        cvt_f16_kernel<<<(n4x + 255) / 256, 256>>>(
            (const float4*)x, (__half2*)x_h, n4x);
        dim3 tblk(32, 8);
        dim3 tg1(3 * DMODEL / 32, DMODEL / 32);
        transpose_f16_kernel<<<tg1, tblk>>>(w_qkv, (__half*)wqkv_h,
                                            DMODEL, 3 * DMODEL);
        dim3 tg2(DMODEL / 32, DMODEL / 32);
        transpose_f16_kernel<<<tg2, tblk>>>(w_proj, (__half*)wproj_h,
                                            DMODEL, DMODEL);
    }

    // 1) QKV projection (fp16 MMA, fp16 output)
    {
        dim3 grid(3 * DMODEL / GBN, MTOK / GBM);
        f16_gemm_kernel<<<grid, 256, GEMM_SMEM_BYTES>>>(
            (const __half*)x_h, (const __half*)wqkv_h, b_qkv,
            nullptr, (__half*)qkv_h, MTOK, 3 * DMODEL, DMODEL);
    }

    // 2) causal flash attention (fp16 MMA, cp.async double-buffered K/V)
    {
        dim3 grid(S_LEN / 64, BATCH * NHEAD);
        attn_mma_kernel<<<grid, 128, ATTN_SMEM_BYTES>>>();
    }

    // 3) output projection (fp16 MMA, fp32 output)
    {
        dim3 grid(DMODEL / GBN, MTOK / GBM);
        f16_gemm_kernel<<<grid, 256, GEMM_SMEM_BYTES>>>(
            (const __half*)attn_h, (const __half*)wproj_h, b_proj,
            out, nullptr, MTOK, DMODEL, DMODEL);
    }
}